// round 7
// baseline (speedup 1.0000x reference)
#include <cuda_runtime.h>
#include <math.h>

// Problem constants
#define BB 8
#define LL 1024
#define DD 512
#define HH 8
#define DH 64
#define INNER 512
#define ROWS (BB*LL)          // 8192
#define EPSV 1e-5f

// ---------------- scratch (device globals; no allocation) ----------------
__device__ float  g_xn [ROWS*DD];
__device__ float  g_pe [LL*DD];
__device__ float  g_pos[HH*LL*DH];
__device__ float  g_q  [BB*HH*LL*DH];
__device__ float  g_k  [BB*HH*LL*DH];
__device__ float  g_v  [BB*HH*LL*DH];
__device__ float  g_att[ROWS*INNER];
__device__ float  g_wqkv[3*INNER*DD];
__device__ float  g_wpos[INNER*DD];
__device__ float  g_wout[DD*INNER];
__device__ double g_freq[DD];

// ---------------- tf32 + cp.async helpers ----------------
__device__ __forceinline__ unsigned f2tf(float x) {
    unsigned r; asm("cvt.rna.tf32.f32 %0, %1;" : "=r"(r) : "f"(x)); return r;
}
__device__ __forceinline__ float f2tff(float x) { return __uint_as_float(f2tf(x)); }

__device__ __forceinline__ void mma_tf32(float c[4], const unsigned a[4], const unsigned b[2]) {
    asm volatile(
        "mma.sync.aligned.m16n8k8.row.col.f32.tf32.tf32.f32 "
        "{%0,%1,%2,%3}, {%4,%5,%6,%7}, {%8,%9}, {%0,%1,%2,%3};"
        : "+f"(c[0]), "+f"(c[1]), "+f"(c[2]), "+f"(c[3])
        : "r"(a[0]), "r"(a[1]), "r"(a[2]), "r"(a[3]), "r"(b[0]), "r"(b[1]));
}

__device__ __forceinline__ void cpa16(float* dst_smem, const float* src) {
    unsigned d = (unsigned)__cvta_generic_to_shared(dst_smem);
    asm volatile("cp.async.cg.shared.global [%0], [%1], 16;" :: "r"(d), "l"(src));
}
#define CP_COMMIT asm volatile("cp.async.commit_group;")
#define CP_WAIT0  asm volatile("cp.async.wait_group 0;")

// ---------------- round weights to tf32 (once per call, tiny) -------------
__global__ void round_w(const float* __restrict__ wq, const float* __restrict__ wp,
                        const float* __restrict__ wo) {
    const int n1 = 3*INNER*DD/4, n2 = INNER*DD/4, n3 = DD*INNER/4;
    int i = blockIdx.x * blockDim.x + threadIdx.x;
    float4 v; float4* dst;
    if (i < n1) {
        v = ((const float4*)wq)[i]; dst = ((float4*)g_wqkv) + i;
    } else if (i < n1 + n2) {
        v = ((const float4*)wp)[i - n1]; dst = ((float4*)g_wpos) + (i - n1);
    } else if (i < n1 + n2 + n3) {
        v = ((const float4*)wo)[i - n1 - n2]; dst = ((float4*)g_wout) + (i - n1 - n2);
    } else return;
    float4 w; w.x = f2tff(v.x); w.y = f2tff(v.y); w.z = f2tff(v.z); w.w = f2tff(v.w);
    *dst = w;
}

// ---------------- freq table (fp64, tiny) ----------------
__global__ void freq_kernel() {
    int j = threadIdx.x + blockIdx.x * blockDim.x;
    if (j < DD) g_freq[j] = exp(-(double)j * (log(10000.0) / 256.0));
}

// ---------------- fused LayerNorm + PE table ----------------
__global__ void ln_pe_kernel(const float* __restrict__ x,
                             const float* __restrict__ gamma,
                             const float* __restrict__ beta,
                             float* __restrict__ xn,
                             float* __restrict__ pe) {
    if (blockIdx.x < ROWS) {
        int row = blockIdx.x;
        const float* xr = x + (size_t)row * DD;
        int t = threadIdx.x;                       // 256 threads
        float a = xr[t], b = xr[t + 256];
        float s = a + b, sq = a*a + b*b;
        #pragma unroll
        for (int o = 16; o; o >>= 1) {
            s  += __shfl_xor_sync(0xffffffffu, s,  o);
            sq += __shfl_xor_sync(0xffffffffu, sq, o);
        }
        __shared__ float ss[8], ssq[8];
        if ((t & 31) == 0) { ss[t >> 5] = s; ssq[t >> 5] = sq; }
        __syncthreads();
        float ts = 0.f, tsq = 0.f;
        #pragma unroll
        for (int i = 0; i < 8; i++) { ts += ss[i]; tsq += ssq[i]; }
        float mu  = ts * (1.f / DD);
        float var = fmaxf(tsq * (1.f / DD) - mu * mu, 0.f);
        float rs  = rsqrtf(var + EPSV);
        float* o = xn + (size_t)row * DD;
        o[t]       = f2tff((a - mu) * rs * gamma[t]       + beta[t]);
        o[t + 256] = f2tff((b - mu) * rs * gamma[t + 256] + beta[t + 256]);
    } else {
        int idx = (blockIdx.x - ROWS) * 256 + threadIdx.x;
        if (idx >= LL * DD) return;
        int i = idx >> 9;
        int j = idx & 511;
        double angle = (double)(i - j) * g_freq[j];
        double n = rint(angle * 0.15915494309189535);   // 1/(2*pi)
        double r = angle - n * 6.283185307179586;       // reduced to [-pi, pi]
        float rf = (float)r;
        pe[idx] = f2tff(((j & 1) == 0) ? cosf(rf) : sinf(rf));
    }
}

// ---------------- TF32 TC GEMM body, 128x128 tile, cp.async double buffer --
// All operands pre-rounded to tf32; fragment loads are plain LDS.
// MODE 0: row-major C; MODE 1: scatter q/k/v; MODE 2: scatter g_pos.
#define GLD 36
#define GSTAGE (128 * GLD)
template<int MODE>
__device__ __forceinline__ void gemm_body(float* As, float* Bs,
                        const float* __restrict__ A, const float* __restrict__ Bt,
                        const float* __restrict__ bias, float* __restrict__ C,
                        int M, int N, int K, int bxx, int byy) {
    int tid  = threadIdx.x, lane = tid & 31, warp = tid >> 5;
    int wm = warp >> 2, wn = warp & 3;
    int g  = lane >> 2, t4 = lane & 3;
    int bm = byy * 128, bn = bxx * 128;

    float c[4][4][4];
    #pragma unroll
    for (int mt = 0; mt < 4; mt++)
        #pragma unroll
        for (int nt = 0; nt < 4; nt++)
            #pragma unroll
            for (int i = 0; i < 4; i++) c[mt][nt][i] = 0.f;

    int nstg = K >> 5;   // K/32
    int ldr = tid >> 1, ldc = (tid & 1) << 4;   // 256 thr -> 128 rows x 2 cols(16)
    {
        const float* a0 = A  + (size_t)(bm + ldr) * K + ldc;
        const float* b0 = Bt + (size_t)(bn + ldr) * K + ldc;
        float* da = As + ldr * GLD + ldc;
        float* db = Bs + ldr * GLD + ldc;
        cpa16(da, a0); cpa16(da + 4, a0 + 4); cpa16(da + 8, a0 + 8); cpa16(da + 12, a0 + 12);
        cpa16(db, b0); cpa16(db + 4, b0 + 4); cpa16(db + 8, b0 + 8); cpa16(db + 12, b0 + 12);
        CP_COMMIT;
    }
    for (int s = 0; s < nstg; s++) {
        CP_WAIT0; __syncthreads();
        if (s + 1 < nstg) {
            int buf = (s + 1) & 1, k0 = (s + 1) << 5;
            const float* a0 = A  + (size_t)(bm + ldr) * K + k0 + ldc;
            const float* b0 = Bt + (size_t)(bn + ldr) * K + k0 + ldc;
            float* da = As + buf * GSTAGE + ldr * GLD + ldc;
            float* db = Bs + buf * GSTAGE + ldr * GLD + ldc;
            cpa16(da, a0); cpa16(da + 4, a0 + 4); cpa16(da + 8, a0 + 8); cpa16(da + 12, a0 + 12);
            cpa16(db, b0); cpa16(db + 4, b0 + 4); cpa16(db + 8, b0 + 8); cpa16(db + 12, b0 + 12);
            CP_COMMIT;
        }
        const float* Ab = As + (s & 1) * GSTAGE;
        const float* Bb = Bs + (s & 1) * GSTAGE;
        #pragma unroll
        for (int kk = 0; kk < 32; kk += 8) {
            unsigned a[4][4], b[4][2];
            #pragma unroll
            for (int mt = 0; mt < 4; mt++) {
                const float* ap = Ab + (wm*64 + mt*16 + g) * GLD + kk + t4;
                a[mt][0] = __float_as_uint(ap[0]);
                a[mt][1] = __float_as_uint(ap[8 * GLD]);
                a[mt][2] = __float_as_uint(ap[4]);
                a[mt][3] = __float_as_uint(ap[8 * GLD + 4]);
            }
            #pragma unroll
            for (int nt = 0; nt < 4; nt++) {
                const float* bp = Bb + (wn*32 + nt*8 + g) * GLD + kk + t4;
                b[nt][0] = __float_as_uint(bp[0]);
                b[nt][1] = __float_as_uint(bp[4]);
            }
            #pragma unroll
            for (int mt = 0; mt < 4; mt++)
                #pragma unroll
                for (int nt = 0; nt < 4; nt++)
                    mma_tf32(c[mt][nt], a[mt], b[nt]);
        }
        __syncthreads();
    }

    // epilogue
    #pragma unroll
    for (int mt = 0; mt < 4; mt++) {
        #pragma unroll
        for (int nt = 0; nt < 4; nt++) {
            int r0 = bm + wm*64 + mt*16 + g;
            int c0 = bn + wn*32 + nt*8 + t4*2;
            #pragma unroll
            for (int e = 0; e < 4; e++) {
                int r = r0 + ((e >> 1) ? 8 : 0);
                int cc = c0 + (e & 1);
                float val = c[mt][nt][e] + (bias ? bias[cc] : 0.f);
                if (MODE == 0) {
                    C[(size_t)r * N + cc] = val;            // final output: full fp32
                } else if (MODE == 1) {
                    int which = cc >> 9, rem = cc & 511;
                    int h = rem >> 6, dh = rem & 63;
                    int b_ = r >> 10, l = r & 1023;
                    float* dst = (which == 0) ? g_q : (which == 1) ? g_k : g_v;
                    dst[(((size_t)b_ * HH + h) * LL + l) * DH + dh] = f2tff(val);
                } else {
                    int h = cc >> 6, dh = cc & 63;
                    g_pos[((size_t)h * LL + r) * DH + dh] = f2tff(val);
                }
            }
        }
    }
}

// fused QKV + pos GEMM (z=0: QKV, z=1: pos). launch_bounds(256,2): 2 CTAs/SM.
__global__ __launch_bounds__(256, 2) void gemm_fused(const float* __restrict__ b_qkv) {
    __shared__ float As[2 * GSTAGE];
    __shared__ float Bs[2 * GSTAGE];
    if (blockIdx.z == 0) {
        gemm_body<1>(As, Bs, g_xn, g_wqkv, b_qkv, nullptr, ROWS, 3*INNER, DD,
                     blockIdx.x, blockIdx.y);
    } else {
        if (blockIdx.x >= INNER/128 || blockIdx.y >= LL/128) return;
        gemm_body<2>(As, Bs, g_pe, g_wpos, nullptr, nullptr, LL, INNER, DD,
                     blockIdx.x, blockIdx.y);
    }
}

// out projection
__global__ __launch_bounds__(256, 2) void gemm_out(const float* __restrict__ b_out,
                                                   float* __restrict__ out) {
    __shared__ float As[2 * GSTAGE];
    __shared__ float Bs[2 * GSTAGE];
    gemm_body<0>(As, Bs, g_att, g_wout, b_out, out, ROWS, DD, INNER,
                 blockIdx.x, blockIdx.y);
}

// ---------------- flash attention, TF32 mma, 512 threads --------------------
// Q-tile 128 rows, KV-tile 64 keys, 16 warps = 8(m) x 2(n), warp tile 16x32.
// All global operands pre-rounded to tf32.
#define SA_LD  132
#define SKP_LD 132
#define SV_LD  72
#define SC_LD  68
#define AT_OFF_KP  (128 * SA_LD)
#define AT_OFF_V   (AT_OFF_KP + 2 * 64 * SKP_LD)
#define AT_OFF_SC  (AT_OFF_V  + 2 * 64 * SV_LD)
#define AT_OFF_AL  (AT_OFF_SC + 128 * SC_LD)
#define AT_OFF_LI  (AT_OFF_AL + 128)
#define AT_SMEM_FLOATS (AT_OFF_LI + 128)
#define ATH 512

__global__ __launch_bounds__(ATH) void attn_tc(const float* __restrict__ u_bias,
                                               const float* __restrict__ v_bias) {
    extern __shared__ float sm[];
    float* sA  = sm;
    float* sKP = sm + AT_OFF_KP;
    float* sV  = sm + AT_OFF_V;
    float* ssc = sm + AT_OFF_SC;
    float* sal = sm + AT_OFF_AL;
    float* sli = sm + AT_OFF_LI;

    int tid = threadIdx.x, lane = tid & 31, warp = tid >> 5;   // 16 warps
    int wm = warp >> 1, wn = warp & 1;                         // 8 x 2
    int g  = lane >> 2, t4 = lane & 3;
    int bh = blockIdx.y, b = bh >> 3, h = bh & 7;
    int q0 = blockIdx.x * 128;

    const float* qb = g_q   + (size_t)bh * LL * DH;
    const float* kb = g_k   + (size_t)bh * LL * DH;
    const float* vb = g_v   + (size_t)bh * LL * DH;
    const float* pb = g_pos + (size_t)h  * LL * DH;

    // prologue: stage 0 of K|P and V
    for (int idx = tid; idx < 1024; idx += ATH) {
        int m = idx >> 4, c4 = (idx & 15) << 2;
        size_t go = (size_t)m * DH + c4;
        cpa16(sKP + m * SKP_LD + c4,      kb + go);
        cpa16(sKP + m * SKP_LD + 64 + c4, pb + go);
        cpa16(sV  + m * SV_LD  + c4,      vb + go);
    }
    CP_COMMIT;

    // build sA = [Q+u | Q+v] tf32-rounded
    for (int idx = tid; idx < 2048; idx += ATH) {
        int r = idx >> 4, c4 = (idx & 15) << 2;
        float4 q4 = *(const float4*)(qb + (size_t)(q0 + r) * DH + c4);
        float4 u4 = *(const float4*)(u_bias + h * DH + c4);
        float4 v4 = *(const float4*)(v_bias + h * DH + c4);
        float4 w1; w1.x = f2tff(q4.x + u4.x); w1.y = f2tff(q4.y + u4.y);
                   w1.z = f2tff(q4.z + u4.z); w1.w = f2tff(q4.w + u4.w);
        float4 w2; w2.x = f2tff(q4.x + v4.x); w2.y = f2tff(q4.y + v4.y);
                   w2.z = f2tff(q4.z + v4.z); w2.w = f2tff(q4.w + v4.w);
        *(float4*)(sA + r * SA_LD + c4)      = w1;
        *(float4*)(sA + r * SA_LD + 64 + c4) = w2;
    }

    int srow = tid >> 2, ssub = tid & 3;    // softmax: 4 threads/row, 16 cols each
    float mi = -INFINITY, li = 0.f;
    float o[4][4];
    #pragma unroll
    for (int nt = 0; nt < 4; nt++)
        #pragma unroll
        for (int i = 0; i < 4; i++) o[nt][i] = 0.f;

    for (int kt = 0; kt < LL / 64; kt++) {
        CP_WAIT0;
        __syncthreads();
        int cur = kt & 1;
        if (kt + 1 < LL / 64) {
            int nb = (kt + 1) & 1;
            float* dKP = sKP + nb * 64 * SKP_LD;
            float* dV  = sV  + nb * 64 * SV_LD;
            for (int idx = tid; idx < 1024; idx += ATH) {
                int m = idx >> 4, c4 = (idx & 15) << 2;
                size_t go = (size_t)((kt + 1) * 64 + m) * DH + c4;
                cpa16(dKP + m * SKP_LD + c4,      kb + go);
                cpa16(dKP + m * SKP_LD + 64 + c4, pb + go);
                cpa16(dV  + m * SV_LD  + c4,      vb + go);
            }
            CP_COMMIT;
        }
        const float* KPb = sKP + cur * 64 * SKP_LD;
        const float* Vb  = sV  + cur * 64 * SV_LD;

        // scores: each warp 16(m) x 32(n), K=128
        float s[4][4];
        #pragma unroll
        for (int nt = 0; nt < 4; nt++)
            #pragma unroll
            for (int i = 0; i < 4; i++) s[nt][i] = 0.f;
        #pragma unroll
        for (int kk = 0; kk < 128; kk += 8) {
            unsigned a[4], bf[4][2];
            const float* ap = sA + (wm*16 + g) * SA_LD + kk + t4;
            a[0] = __float_as_uint(ap[0]);
            a[1] = __float_as_uint(ap[8 * SA_LD]);
            a[2] = __float_as_uint(ap[4]);
            a[3] = __float_as_uint(ap[8 * SA_LD + 4]);
            #pragma unroll
            for (int nt = 0; nt < 4; nt++) {
                const float* bp = KPb + (wn*32 + nt*8 + g) * SKP_LD + kk + t4;
                bf[nt][0] = __float_as_uint(bp[0]);
                bf[nt][1] = __float_as_uint(bp[4]);
            }
            #pragma unroll
            for (int nt = 0; nt < 4; nt++)
                mma_tf32(s[nt], a, bf[nt]);
        }
        #pragma unroll
        for (int nt = 0; nt < 4; nt++) {
            float* d = ssc + (wm*16 + g) * SC_LD + wn*32 + nt*8 + t4*2;
            float2 lo; lo.x = s[nt][0] * 0.125f; lo.y = s[nt][1] * 0.125f;
            float2 hi; hi.x = s[nt][2] * 0.125f; hi.y = s[nt][3] * 0.125f;
            *(float2*)d             = lo;
            *(float2*)(d + 8*SC_LD) = hi;
        }
        __syncthreads();

        // online softmax (4 threads per row, 16 scores each)
        {
            float* rp = ssc + srow * SC_LD + ssub * 16;
            float tm = -INFINITY;
            #pragma unroll
            for (int i = 0; i < 16; i++) tm = fmaxf(tm, rp[i]);
            tm = fmaxf(tm, __shfl_xor_sync(0xffffffffu, tm, 1));
            tm = fmaxf(tm, __shfl_xor_sync(0xffffffffu, tm, 2));
            float newm = fmaxf(mi, tm);
            float alpha = __expf(mi - newm);
            float ls = 0.f;
            #pragma unroll
            for (int i = 0; i < 16; i++) {
                float p = __expf(rp[i] - newm);
                ls += p;
                rp[i] = f2tff(p);
            }
            ls += __shfl_xor_sync(0xffffffffu, ls, 1);
            ls += __shfl_xor_sync(0xffffffffu, ls, 2);
            li = li * alpha + ls;
            mi = newm;
            if (ssub == 0) sal[srow] = alpha;
        }
        __syncthreads();

        // AV: O = O*alpha + P.V  (warp 16x32, K=64)
        {
            float aa = sal[wm*16 + g];
            float ab = sal[wm*16 + g + 8];
            #pragma unroll
            for (int nt = 0; nt < 4; nt++) {
                o[nt][0] *= aa; o[nt][1] *= aa;
                o[nt][2] *= ab; o[nt][3] *= ab;
            }
            #pragma unroll
            for (int kk = 0; kk < 64; kk += 8) {
                unsigned a[4], bf[4][2];
                const float* ap = ssc + (wm*16 + g) * SC_LD + kk + t4;
                a[0] = __float_as_uint(ap[0]);
                a[1] = __float_as_uint(ap[8 * SC_LD]);
                a[2] = __float_as_uint(ap[4]);
                a[3] = __float_as_uint(ap[8 * SC_LD + 4]);
                #pragma unroll
                for (int nt = 0; nt < 4; nt++) {
                    const float* bp = Vb + (kk + t4) * SV_LD + wn*32 + nt*8 + g;
                    bf[nt][0] = __float_as_uint(bp[0]);
                    bf[nt][1] = __float_as_uint(bp[4 * SV_LD]);
                }
                #pragma unroll
                for (int nt = 0; nt < 4; nt++)
                    mma_tf32(o[nt], a, bf[nt]);
            }
        }
    }

    // finalize (round for the out-projection's tf32 A operand)
    if (ssub == 0) sli[srow] = li;
    __syncthreads();
    {
        int r0 = wm*16 + g;
        float inva = 1.f / sli[r0];
        float invb = 1.f / sli[r0 + 8];
        #pragma unroll
        for (int nt = 0; nt < 4; nt++) {
            int dh0 = wn*32 + nt*8 + t4*2;
            float* o1 = g_att + ((size_t)(b * LL + q0 + r0))     * INNER + h * DH + dh0;
            float* o2 = g_att + ((size_t)(b * LL + q0 + r0 + 8)) * INNER + h * DH + dh0;
            o1[0] = f2tff(o[nt][0] * inva); o1[1] = f2tff(o[nt][1] * inva);
            o2[0] = f2tff(o[nt][2] * invb); o2[1] = f2tff(o[nt][3] * invb);
        }
    }
}

// ---------------- launch ----------------
extern "C" void kernel_launch(void* const* d_in, const int* in_sizes, int n_in,
                              void* d_out, int out_size) {
    const float* x      = (const float*)d_in[0];
    const float* gamma  = (const float*)d_in[1];
    const float* beta   = (const float*)d_in[2];
    const float* w_qkv  = (const float*)d_in[3];
    const float* b_qkv  = (const float*)d_in[4];
    const float* w_pos  = (const float*)d_in[5];
    const float* w_out  = (const float*)d_in[6];
    const float* b_out  = (const float*)d_in[7];
    const float* u_bias = (const float*)d_in[8];
    const float* v_bias = (const float*)d_in[9];
    float* out = (float*)d_out;

    float *p_xn, *p_pe;
    cudaGetSymbolAddress((void**)&p_xn, g_xn);
    cudaGetSymbolAddress((void**)&p_pe, g_pe);

    // 1. round weights to tf32 + freq table (independent, tiny)
    {
        int n4 = (3*INNER*DD + INNER*DD + DD*INNER) / 4;
        round_w<<<(n4 + 255) / 256, 256>>>(w_qkv, w_pos, w_out);
        freq_kernel<<<2, 256>>>();
    }

    // 2. fused LayerNorm + PE table
    ln_pe_kernel<<<ROWS + (LL*DD)/256, 256>>>(x, gamma, beta, p_xn, p_pe);

    // 3. fused QKV GEMM + pos GEMM
    {
        dim3 grid((3 * INNER) / 128, ROWS / 128, 2);
        gemm_fused<<<grid, 256>>>(b_qkv);
    }

    // 4. attention
    {
        int smem = AT_SMEM_FLOATS * (int)sizeof(float);   // ~208 KB
        cudaFuncSetAttribute(attn_tc, cudaFuncAttributeMaxDynamicSharedMemorySize, smem);
        dim3 grid(LL / 128, BB * HH);
        attn_tc<<<grid, ATH, smem>>>(u_bias, v_bias);
    }

    // 5. out projection -> d_out
    {
        dim3 grid(DD / 128, ROWS / 128);
        gemm_out<<<grid, 256>>>(b_out, out);
    }
}

// round 8
// speedup vs baseline: 1.5151x; 1.5151x over previous
#include <cuda_runtime.h>
#include <cuda_fp16.h>
#include <math.h>

// Problem constants
#define BB 8
#define LL 1024
#define DD 512
#define HH 8
#define DH 64
#define INNER 512
#define ROWS (BB*LL)          // 8192
#define EPSV 1e-5f

// ---------------- scratch (device globals; no allocation) ----------------
__device__ __half  g_xn [ROWS*DD];
__device__ __half  g_pe [LL*DD];
__device__ __half  g_pos[HH*LL*DH];
__device__ __half  g_q  [BB*HH*LL*DH];
__device__ __half  g_k  [BB*HH*LL*DH];
__device__ __half  g_v  [BB*HH*DH*LL];     // TRANSPOSED: [bh][dh][l]
__device__ __half  g_att[ROWS*INNER];
__device__ __half  g_wqkv[3*INNER*DD];
__device__ __half  g_wpos[INNER*DD];
__device__ __half  g_wout[DD*INNER];
__device__ double  g_freq[DD];

// ---------------- helpers ----------------
__device__ __forceinline__ void mma_f16(float c[4], const unsigned a[4], const unsigned b[2]) {
    asm volatile(
        "mma.sync.aligned.m16n8k16.row.col.f32.f16.f16.f32 "
        "{%0,%1,%2,%3}, {%4,%5,%6,%7}, {%8,%9}, {%0,%1,%2,%3};"
        : "+f"(c[0]), "+f"(c[1]), "+f"(c[2]), "+f"(c[3])
        : "r"(a[0]), "r"(a[1]), "r"(a[2]), "r"(a[3]), "r"(b[0]), "r"(b[1]));
}

__device__ __forceinline__ void cpa16(void* dst_smem, const void* src) {
    unsigned d = (unsigned)__cvta_generic_to_shared(dst_smem);
    asm volatile("cp.async.cg.shared.global [%0], [%1], 16;" :: "r"(d), "l"(src));
}
#define CP_COMMIT asm volatile("cp.async.commit_group;")
#define CP_WAIT0  asm volatile("cp.async.wait_group 0;")

// ---------------- convert weights to half (once per call, tiny) -----------
__global__ void cvt_w(const float* __restrict__ wq, const float* __restrict__ wp,
                      const float* __restrict__ wo) {
    const int n1 = 3*INNER*DD/4, n2 = INNER*DD/4, n3 = DD*INNER/4;
    int i = blockIdx.x * blockDim.x + threadIdx.x;
    float4 v; __half* dst;
    if (i < n1) {
        v = ((const float4*)wq)[i]; dst = g_wqkv + 4*i;
    } else if (i < n1 + n2) {
        v = ((const float4*)wp)[i - n1]; dst = g_wpos + 4*(i - n1);
    } else if (i < n1 + n2 + n3) {
        v = ((const float4*)wo)[i - n1 - n2]; dst = g_wout + 4*(i - n1 - n2);
    } else return;
    *(__half2*)(dst)     = __floats2half2_rn(v.x, v.y);
    *(__half2*)(dst + 2) = __floats2half2_rn(v.z, v.w);
}

// ---------------- freq table (fp64, tiny) ----------------
__global__ void freq_kernel() {
    int j = threadIdx.x + blockIdx.x * blockDim.x;
    if (j < DD) g_freq[j] = exp(-(double)j * (log(10000.0) / 256.0));
}

// ---------------- fused LayerNorm + PE table ----------------
__global__ void ln_pe_kernel(const float* __restrict__ x,
                             const float* __restrict__ gamma,
                             const float* __restrict__ beta) {
    if (blockIdx.x < ROWS) {
        int row = blockIdx.x;
        const float* xr = x + (size_t)row * DD;
        int t = threadIdx.x;                       // 256 threads
        float a = xr[t], b = xr[t + 256];
        float s = a + b, sq = a*a + b*b;
        #pragma unroll
        for (int o = 16; o; o >>= 1) {
            s  += __shfl_xor_sync(0xffffffffu, s,  o);
            sq += __shfl_xor_sync(0xffffffffu, sq, o);
        }
        __shared__ float ss[8], ssq[8];
        if ((t & 31) == 0) { ss[t >> 5] = s; ssq[t >> 5] = sq; }
        __syncthreads();
        float ts = 0.f, tsq = 0.f;
        #pragma unroll
        for (int i = 0; i < 8; i++) { ts += ss[i]; tsq += ssq[i]; }
        float mu  = ts * (1.f / DD);
        float var = fmaxf(tsq * (1.f / DD) - mu * mu, 0.f);
        float rs  = rsqrtf(var + EPSV);
        __half* o = g_xn + (size_t)row * DD;
        o[t]       = __float2half_rn((a - mu) * rs * gamma[t]       + beta[t]);
        o[t + 256] = __float2half_rn((b - mu) * rs * gamma[t + 256] + beta[t + 256]);
    } else {
        int idx = (blockIdx.x - ROWS) * 256 + threadIdx.x;
        if (idx >= LL * DD) return;
        int i = idx >> 9;
        int j = idx & 511;
        double angle = (double)(i - j) * g_freq[j];
        double n = rint(angle * 0.15915494309189535);   // 1/(2*pi)
        double r = angle - n * 6.283185307179586;       // reduced to [-pi, pi]
        float rf = (float)r;
        g_pe[idx] = __float2half_rn(((j & 1) == 0) ? cosf(rf) : sinf(rf));
    }
}

// ---------------- FP16 TC GEMM body, 128x128 tile, K-stage 64, dbl buffer --
// C[M,N] = A[M,K] * Bt[N,K]^T (+bias); A,Bt are half; accum fp32.
// MODE 0: fp32 row-major C; MODE 1: scatter q/k/v-transposed; MODE 2: g_pos.
#define HLD 72
#define GSTAGE (128 * HLD)
template<int MODE>
__device__ __forceinline__ void gemm_body(__half* As, __half* Bs,
                        const __half* __restrict__ A, const __half* __restrict__ Bt,
                        const float* __restrict__ bias, float* __restrict__ C,
                        int M, int N, int K, int bxx, int byy) {
    int tid  = threadIdx.x, lane = tid & 31, warp = tid >> 5;
    int wm = warp >> 2, wn = warp & 3;     // 2 x 4, warp tile 64x32
    int g  = lane >> 2, t4 = lane & 3;
    int bm = byy * 128, bn = bxx * 128;

    float c[4][4][4];
    #pragma unroll
    for (int mt = 0; mt < 4; mt++)
        #pragma unroll
        for (int nt = 0; nt < 4; nt++)
            #pragma unroll
            for (int i = 0; i < 4; i++) c[mt][nt][i] = 0.f;

    int nstg = K >> 6;   // K/64
    int ldr = tid >> 1, ldc = (tid & 1) << 5;   // 128 rows x 2 half-chunks(32)
    {
        const __half* a0 = A  + (size_t)(bm + ldr) * K + ldc;
        const __half* b0 = Bt + (size_t)(bn + ldr) * K + ldc;
        __half* da = As + ldr * HLD + ldc;
        __half* db = Bs + ldr * HLD + ldc;
        cpa16(da, a0); cpa16(da + 8, a0 + 8); cpa16(da + 16, a0 + 16); cpa16(da + 24, a0 + 24);
        cpa16(db, b0); cpa16(db + 8, b0 + 8); cpa16(db + 16, b0 + 16); cpa16(db + 24, b0 + 24);
        CP_COMMIT;
    }
    for (int s = 0; s < nstg; s++) {
        CP_WAIT0; __syncthreads();
        if (s + 1 < nstg) {
            int buf = (s + 1) & 1, k0 = (s + 1) << 6;
            const __half* a0 = A  + (size_t)(bm + ldr) * K + k0 + ldc;
            const __half* b0 = Bt + (size_t)(bn + ldr) * K + k0 + ldc;
            __half* da = As + buf * GSTAGE + ldr * HLD + ldc;
            __half* db = Bs + buf * GSTAGE + ldr * HLD + ldc;
            cpa16(da, a0); cpa16(da + 8, a0 + 8); cpa16(da + 16, a0 + 16); cpa16(da + 24, a0 + 24);
            cpa16(db, b0); cpa16(db + 8, b0 + 8); cpa16(db + 16, b0 + 16); cpa16(db + 24, b0 + 24);
            CP_COMMIT;
        }
        const __half* Ab = As + (s & 1) * GSTAGE;
        const __half* Bb = Bs + (s & 1) * GSTAGE;
        #pragma unroll
        for (int kk = 0; kk < 64; kk += 16) {
            unsigned a[4][4], b[4][2];
            #pragma unroll
            for (int mt = 0; mt < 4; mt++) {
                const __half* ap = Ab + (wm*64 + mt*16 + g) * HLD + kk + 2*t4;
                a[mt][0] = *(const unsigned*)(ap);
                a[mt][1] = *(const unsigned*)(ap + 8 * HLD);
                a[mt][2] = *(const unsigned*)(ap + 8);
                a[mt][3] = *(const unsigned*)(ap + 8 * HLD + 8);
            }
            #pragma unroll
            for (int nt = 0; nt < 4; nt++) {
                const __half* bp = Bb + (wn*32 + nt*8 + g) * HLD + kk + 2*t4;
                b[nt][0] = *(const unsigned*)(bp);
                b[nt][1] = *(const unsigned*)(bp + 8);
            }
            #pragma unroll
            for (int mt = 0; mt < 4; mt++)
                #pragma unroll
                for (int nt = 0; nt < 4; nt++)
                    mma_f16(c[mt][nt], a[mt], b[nt]);
        }
        __syncthreads();
    }

    // epilogue
    #pragma unroll
    for (int mt = 0; mt < 4; mt++) {
        #pragma unroll
        for (int nt = 0; nt < 4; nt++) {
            int r0 = bm + wm*64 + mt*16 + g;
            int c0 = bn + wn*32 + nt*8 + t4*2;
            #pragma unroll
            for (int e = 0; e < 4; e++) {
                int r = r0 + ((e >> 1) ? 8 : 0);
                int cc = c0 + (e & 1);
                float val = c[mt][nt][e] + (bias ? bias[cc] : 0.f);
                if (MODE == 0) {
                    C[(size_t)r * N + cc] = val;            // final output: fp32
                } else if (MODE == 1) {
                    int which = cc >> 9, rem = cc & 511;
                    int h = rem >> 6, dh = rem & 63;
                    int b_ = r >> 10, l = r & 1023;
                    __half hv = __float2half_rn(val);
                    if (which == 0)
                        g_q[(((size_t)b_ * HH + h) * LL + l) * DH + dh] = hv;
                    else if (which == 1)
                        g_k[(((size_t)b_ * HH + h) * LL + l) * DH + dh] = hv;
                    else  // V transposed: [bh][dh][l]
                        g_v[(((size_t)b_ * HH + h) * DH + dh) * LL + l] = hv;
                } else {
                    int h = cc >> 6, dh = cc & 63;
                    g_pos[((size_t)h * LL + r) * DH + dh] = __float2half_rn(val);
                }
            }
        }
    }
}

// fused QKV + pos GEMM (z=0: QKV, z=1: pos). 2 CTAs/SM.
__global__ __launch_bounds__(256, 2) void gemm_fused(const float* __restrict__ b_qkv) {
    __shared__ __half As[2 * GSTAGE];
    __shared__ __half Bs[2 * GSTAGE];
    if (blockIdx.z == 0) {
        gemm_body<1>(As, Bs, g_xn, g_wqkv, b_qkv, nullptr, ROWS, 3*INNER, DD,
                     blockIdx.x, blockIdx.y);
    } else {
        if (blockIdx.x >= INNER/128 || blockIdx.y >= LL/128) return;
        gemm_body<2>(As, Bs, g_pe, g_wpos, nullptr, nullptr, LL, INNER, DD,
                     blockIdx.x, blockIdx.y);
    }
}

// out projection
__global__ __launch_bounds__(256, 2) void gemm_out(const float* __restrict__ b_out,
                                                   float* __restrict__ out) {
    __shared__ __half As[2 * GSTAGE];
    __shared__ __half Bs[2 * GSTAGE];
    gemm_body<0>(As, Bs, g_att, g_wout, b_out, out, ROWS, DD, INNER,
                 blockIdx.x, blockIdx.y);
}

// ---------------- flash attention, FP16 mma, 256 threads -------------------
// Q-tile 128, KV-tile 64. 8 warps = 4(m) x 2(n), warp tile 32x32.
// scores = [Q+u|Q+v](128x128h) . [K|P]^T; fp32 softmax; P half; AV with V^T.
#define ATL  136   // sA / sKP row stride (halves)
#define VTL  72    // sVT row stride (halves)
#define SPL  72    // sP row stride (halves)
#define SCLD 68    // ssc row stride (floats)
// half-region sizes
#define N_SA  (128 * ATL)
#define N_SKP (2 * 64 * ATL)
#define N_SVT (2 * 64 * VTL)
#define N_SP  (128 * SPL)
#define ATT_SMEM_BYTES ((N_SA + N_SKP + N_SVT + N_SP) * 2 + (128 * SCLD + 256) * 4)

__global__ __launch_bounds__(256) void attn_tc(const float* __restrict__ u_bias,
                                               const float* __restrict__ v_bias) {
    extern __shared__ char smbase[];
    __half* sA  = (__half*)smbase;
    __half* sKP = sA  + N_SA;
    __half* sVT = sKP + N_SKP;
    __half* sP  = sVT + N_SVT;
    float*  ssc = (float*)(sP + N_SP);
    float*  sal = ssc + 128 * SCLD;
    float*  sli = sal + 128;

    int tid = threadIdx.x, lane = tid & 31, warp = tid >> 5;
    int wm = warp >> 1, wn = warp & 1;       // 4 x 2
    int g  = lane >> 2, t4 = lane & 3;
    int bh = blockIdx.y, b = bh >> 3, h = bh & 7;
    int q0 = blockIdx.x * 128;

    const __half* qb  = g_q   + (size_t)bh * LL * DH;
    const __half* kb  = g_k   + (size_t)bh * LL * DH;
    const __half* vtb = g_v   + (size_t)bh * DH * LL;   // [dh][l]
    const __half* pb  = g_pos + (size_t)h  * LL * DH;

    // prologue: stage 0 of K|P and V^T
    for (int idx = tid; idx < 512; idx += 256) {
        int m = idx >> 3, c8 = (idx & 7) << 3;
        cpa16(sKP + m * ATL + c8,      kb  + (size_t)m * DH + c8);
        cpa16(sKP + m * ATL + 64 + c8, pb  + (size_t)m * DH + c8);
        cpa16(sVT + m * VTL + c8,      vtb + (size_t)m * LL + c8);   // m = dh row
    }
    CP_COMMIT;

    // build sA = [Q+u | Q+v] (half)
    for (int idx = tid; idx < 4096; idx += 256) {
        int r = idx >> 5, c2 = idx & 31;            // half2 index within 64
        float2 qf = __half22float2(*(const __half2*)(qb + (size_t)(q0 + r) * DH + 2*c2));
        float2 uf = *(const float2*)(u_bias + h * DH + 2*c2);
        float2 vf = *(const float2*)(v_bias + h * DH + 2*c2);
        *(__half2*)(sA + r * ATL + 2*c2)      = __floats2half2_rn(qf.x + uf.x, qf.y + uf.y);
        *(__half2*)(sA + r * ATL + 64 + 2*c2) = __floats2half2_rn(qf.x + vf.x, qf.y + vf.y);
    }

    int srow = tid >> 1, ssub = tid & 1;    // softmax: 2 threads/row, 32 cols each
    float mi = -INFINITY, li = 0.f;
    float o[2][4][4];
    #pragma unroll
    for (int mt = 0; mt < 2; mt++)
        #pragma unroll
        for (int nt = 0; nt < 4; nt++)
            #pragma unroll
            for (int i = 0; i < 4; i++) o[mt][nt][i] = 0.f;

    for (int kt = 0; kt < LL / 64; kt++) {
        CP_WAIT0;
        __syncthreads();
        int cur = kt & 1;
        if (kt + 1 < LL / 64) {
            int nb = (kt + 1) & 1;
            __half* dKP = sKP + nb * 64 * ATL;
            __half* dVT = sVT + nb * 64 * VTL;
            int kbase = (kt + 1) * 64;
            for (int idx = tid; idx < 512; idx += 256) {
                int m = idx >> 3, c8 = (idx & 7) << 3;
                cpa16(dKP + m * ATL + c8,      kb  + (size_t)(kbase + m) * DH + c8);
                cpa16(dKP + m * ATL + 64 + c8, pb  + (size_t)(kbase + m) * DH + c8);
                cpa16(dVT + m * VTL + c8,      vtb + (size_t)m * LL + kbase + c8);
            }
            CP_COMMIT;
        }
        const __half* KPb = sKP + cur * 64 * ATL;
        const __half* VTb = sVT + cur * 64 * VTL;

        // scores: 128x64, K=128 (8 k16 steps)
        float s[2][4][4];
        #pragma unroll
        for (int mt = 0; mt < 2; mt++)
            #pragma unroll
            for (int nt = 0; nt < 4; nt++)
                #pragma unroll
                for (int i = 0; i < 4; i++) s[mt][nt][i] = 0.f;
        #pragma unroll
        for (int kk = 0; kk < 128; kk += 16) {
            unsigned a[2][4], bf[4][2];
            #pragma unroll
            for (int mt = 0; mt < 2; mt++) {
                const __half* ap = sA + (wm*32 + mt*16 + g) * ATL + kk + 2*t4;
                a[mt][0] = *(const unsigned*)(ap);
                a[mt][1] = *(const unsigned*)(ap + 8 * ATL);
                a[mt][2] = *(const unsigned*)(ap + 8);
                a[mt][3] = *(const unsigned*)(ap + 8 * ATL + 8);
            }
            #pragma unroll
            for (int nt = 0; nt < 4; nt++) {
                const __half* bp = KPb + (wn*32 + nt*8 + g) * ATL + kk + 2*t4;
                bf[nt][0] = *(const unsigned*)(bp);
                bf[nt][1] = *(const unsigned*)(bp + 8);
            }
            #pragma unroll
            for (int mt = 0; mt < 2; mt++)
                #pragma unroll
                for (int nt = 0; nt < 4; nt++)
                    mma_f16(s[mt][nt], a[mt], bf[nt]);
        }
        #pragma unroll
        for (int mt = 0; mt < 2; mt++)
            #pragma unroll
            for (int nt = 0; nt < 4; nt++) {
                float* d = ssc + (wm*32 + mt*16 + g) * SCLD + wn*32 + nt*8 + t4*2;
                float2 lo; lo.x = s[mt][nt][0] * 0.125f; lo.y = s[mt][nt][1] * 0.125f;
                float2 hi; hi.x = s[mt][nt][2] * 0.125f; hi.y = s[mt][nt][3] * 0.125f;
                *(float2*)d              = lo;
                *(float2*)(d + 8*SCLD)   = hi;
            }
        __syncthreads();

        // online softmax (2 threads per row, 32 scores each); probs -> sP half
        {
            float* rp = ssc + srow * SCLD + ssub * 32;
            __half* pp = sP + srow * SPL + ssub * 32;
            float tm = -INFINITY;
            #pragma unroll
            for (int i = 0; i < 32; i++) tm = fmaxf(tm, rp[i]);
            tm = fmaxf(tm, __shfl_xor_sync(0xffffffffu, tm, 1));
            float newm = fmaxf(mi, tm);
            float alpha = __expf(mi - newm);
            float ls = 0.f;
            #pragma unroll
            for (int i = 0; i < 32; i += 2) {
                float p0 = __expf(rp[i] - newm);
                float p1 = __expf(rp[i+1] - newm);
                ls += p0 + p1;
                *(__half2*)(pp + i) = __floats2half2_rn(p0, p1);
            }
            ls += __shfl_xor_sync(0xffffffffu, ls, 1);
            li = li * alpha + ls;
            mi = newm;
            if (ssub == 0) sal[srow] = alpha;
        }
        __syncthreads();

        // AV: O = O*alpha + P.V  (K=64, 4 k16 steps), B from V^T
        {
            #pragma unroll
            for (int mt = 0; mt < 2; mt++) {
                float aa = sal[wm*32 + mt*16 + g];
                float ab = sal[wm*32 + mt*16 + g + 8];
                #pragma unroll
                for (int nt = 0; nt < 4; nt++) {
                    o[mt][nt][0] *= aa; o[mt][nt][1] *= aa;
                    o[mt][nt][2] *= ab; o[mt][nt][3] *= ab;
                }
            }
            #pragma unroll
            for (int kk = 0; kk < 64; kk += 16) {
                unsigned a[2][4], bf[4][2];
                #pragma unroll
                for (int mt = 0; mt < 2; mt++) {
                    const __half* ap = sP + (wm*32 + mt*16 + g) * SPL + kk + 2*t4;
                    a[mt][0] = *(const unsigned*)(ap);
                    a[mt][1] = *(const unsigned*)(ap + 8 * SPL);
                    a[mt][2] = *(const unsigned*)(ap + 8);
                    a[mt][3] = *(const unsigned*)(ap + 8 * SPL + 8);
                }
                #pragma unroll
                for (int nt = 0; nt < 4; nt++) {
                    const __half* bp = VTb + (wn*32 + nt*8 + g) * VTL + kk + 2*t4;
                    bf[nt][0] = *(const unsigned*)(bp);
                    bf[nt][1] = *(const unsigned*)(bp + 8);
                }
                #pragma unroll
                for (int mt = 0; mt < 2; mt++)
                    #pragma unroll
                    for (int nt = 0; nt < 4; nt++)
                        mma_f16(o[mt][nt], a[mt], bf[nt]);
            }
        }
    }

    // finalize -> g_att (half)
    if (ssub == 0) sli[srow] = li;
    __syncthreads();
    #pragma unroll
    for (int mt = 0; mt < 2; mt++) {
        int r0 = wm*32 + mt*16 + g;
        float inva = 1.f / sli[r0];
        float invb = 1.f / sli[r0 + 8];
        #pragma unroll
        for (int nt = 0; nt < 4; nt++) {
            int dh0 = wn*32 + nt*8 + t4*2;
            __half* o1 = g_att + ((size_t)(b * LL + q0 + r0))     * INNER + h * DH + dh0;
            __half* o2 = g_att + ((size_t)(b * LL + q0 + r0 + 8)) * INNER + h * DH + dh0;
            *(__half2*)o1 = __floats2half2_rn(o[mt][nt][0] * inva, o[mt][nt][1] * inva);
            *(__half2*)o2 = __floats2half2_rn(o[mt][nt][2] * invb, o[mt][nt][3] * invb);
        }
    }
}

// ---------------- launch ----------------
extern "C" void kernel_launch(void* const* d_in, const int* in_sizes, int n_in,
                              void* d_out, int out_size) {
    const float* x      = (const float*)d_in[0];
    const float* gamma  = (const float*)d_in[1];
    const float* beta   = (const float*)d_in[2];
    const float* w_qkv  = (const float*)d_in[3];
    const float* b_qkv  = (const float*)d_in[4];
    const float* w_pos  = (const float*)d_in[5];
    const float* w_out  = (const float*)d_in[6];
    const float* b_out  = (const float*)d_in[7];
    const float* u_bias = (const float*)d_in[8];
    const float* v_bias = (const float*)d_in[9];
    float* out = (float*)d_out;

    // 1. convert weights to half + freq table (independent, tiny)
    {
        int n4 = (3*INNER*DD + INNER*DD + DD*INNER) / 4;
        cvt_w<<<(n4 + 255) / 256, 256>>>(w_qkv, w_pos, w_out);
        freq_kernel<<<2, 256>>>();
    }

    // 2. fused LayerNorm + PE table
    ln_pe_kernel<<<ROWS + (LL*DD)/256, 256>>>(x, gamma, beta);

    // 3. fused QKV GEMM + pos GEMM
    {
        dim3 grid((3 * INNER) / 128, ROWS / 128, 2);
        gemm_fused<<<grid, 256>>>(b_qkv);
    }

    // 4. attention
    {
        int smem = ATT_SMEM_BYTES;   // ~139 KB
        cudaFuncSetAttribute(attn_tc, cudaFuncAttributeMaxDynamicSharedMemorySize, smem);
        dim3 grid(LL / 128, BB * HH);
        attn_tc<<<grid, 256, smem>>>(u_bias, v_bias);
    }

    // 5. out projection -> d_out
    {
        dim3 grid(DD / 128, ROWS / 128);
        gemm_out<<<grid, 256>>>(b_out, out);
    }
}

// round 10
// speedup vs baseline: 2.1245x; 1.4022x over previous
#include <cuda_runtime.h>
#include <cuda_fp16.h>
#include <math.h>

// Problem constants
#define BB 8
#define LL 1024
#define DD 512
#define HH 8
#define DH 64
#define INNER 512
#define ROWS (BB*LL)          // 8192
#define EPSV 1e-5f

// ---------------- scratch (device globals; no allocation) ----------------
__device__ __half  g_xn [ROWS*DD];
__device__ __half  g_pe [LL*DD];
__device__ __half  g_pos[HH*LL*DH];
__device__ __half  g_q  [BB*HH*LL*DH];
__device__ __half  g_k  [BB*HH*LL*DH];
__device__ __half  g_v  [BB*HH*DH*LL];     // TRANSPOSED: [bh][dh][l]
__device__ __half  g_att[ROWS*INNER];
__device__ __half  g_wqkv[3*INNER*DD];
__device__ __half  g_wpos[INNER*DD];
__device__ __half  g_wout[DD*INNER];
__device__ double  g_freq[DD];

// ---------------- helpers ----------------
__device__ __forceinline__ void mma_f16(float c[4], const unsigned a[4], const unsigned b[2]) {
    asm volatile(
        "mma.sync.aligned.m16n8k16.row.col.f32.f16.f16.f32 "
        "{%0,%1,%2,%3}, {%4,%5,%6,%7}, {%8,%9}, {%0,%1,%2,%3};"
        : "+f"(c[0]), "+f"(c[1]), "+f"(c[2]), "+f"(c[3])
        : "r"(a[0]), "r"(a[1]), "r"(a[2]), "r"(a[3]), "r"(b[0]), "r"(b[1]));
}

// pack two fp32 into one f16x2 register (lo = x, hi = y)
__device__ __forceinline__ unsigned pack_h2(float x, float y) {
    unsigned r;
    asm("cvt.rn.f16x2.f32 %0, %1, %2;" : "=r"(r) : "f"(y), "f"(x));
    return r;
}

__device__ __forceinline__ void cpa16(void* dst_smem, const void* src) {
    unsigned d = (unsigned)__cvta_generic_to_shared(dst_smem);
    asm volatile("cp.async.cg.shared.global [%0], [%1], 16;" :: "r"(d), "l"(src));
}
#define CP_COMMIT asm volatile("cp.async.commit_group;")
#define CP_WAIT0  asm volatile("cp.async.wait_group 0;")

// ---------------- convert weights to half (once per call, tiny) -----------
__global__ void cvt_w(const float* __restrict__ wq, const float* __restrict__ wp,
                      const float* __restrict__ wo) {
    const int n1 = 3*INNER*DD/4, n2 = INNER*DD/4, n3 = DD*INNER/4;
    int i = blockIdx.x * blockDim.x + threadIdx.x;
    float4 v; __half* dst;
    if (i < n1) {
        v = ((const float4*)wq)[i]; dst = g_wqkv + 4*i;
    } else if (i < n1 + n2) {
        v = ((const float4*)wp)[i - n1]; dst = g_wpos + 4*(i - n1);
    } else if (i < n1 + n2 + n3) {
        v = ((const float4*)wo)[i - n1 - n2]; dst = g_wout + 4*(i - n1 - n2);
    } else return;
    *(__half2*)(dst)     = __floats2half2_rn(v.x, v.y);
    *(__half2*)(dst + 2) = __floats2half2_rn(v.z, v.w);
}

// ---------------- freq table (fp64, tiny) ----------------
__global__ void freq_kernel() {
    int j = threadIdx.x + blockIdx.x * blockDim.x;
    if (j < DD) g_freq[j] = exp(-(double)j * (log(10000.0) / 256.0));
}

// ---------------- fused LayerNorm + PE table ----------------
__global__ void ln_pe_kernel(const float* __restrict__ x,
                             const float* __restrict__ gamma,
                             const float* __restrict__ beta) {
    if (blockIdx.x < ROWS) {
        int row = blockIdx.x;
        const float* xr = x + (size_t)row * DD;
        int t = threadIdx.x;                       // 256 threads
        float a = xr[t], b = xr[t + 256];
        float s = a + b, sq = a*a + b*b;
        #pragma unroll
        for (int o = 16; o; o >>= 1) {
            s  += __shfl_xor_sync(0xffffffffu, s,  o);
            sq += __shfl_xor_sync(0xffffffffu, sq, o);
        }
        __shared__ float ss[8], ssq[8];
        if ((t & 31) == 0) { ss[t >> 5] = s; ssq[t >> 5] = sq; }
        __syncthreads();
        float ts = 0.f, tsq = 0.f;
        #pragma unroll
        for (int i = 0; i < 8; i++) { ts += ss[i]; tsq += ssq[i]; }
        float mu  = ts * (1.f / DD);
        float var = fmaxf(tsq * (1.f / DD) - mu * mu, 0.f);
        float rs  = rsqrtf(var + EPSV);
        __half* o = g_xn + (size_t)row * DD;
        o[t]       = __float2half_rn((a - mu) * rs * gamma[t]       + beta[t]);
        o[t + 256] = __float2half_rn((b - mu) * rs * gamma[t + 256] + beta[t + 256]);
    } else {
        int idx = (blockIdx.x - ROWS) * 256 + threadIdx.x;
        if (idx >= LL * DD) return;
        int i = idx >> 9;
        int j = idx & 511;
        double angle = (double)(i - j) * g_freq[j];
        double n = rint(angle * 0.15915494309189535);   // 1/(2*pi)
        double r = angle - n * 6.283185307179586;       // reduced to [-pi, pi]
        float rf = (float)r;
        g_pe[idx] = __float2half_rn(((j & 1) == 0) ? cosf(rf) : sinf(rf));
    }
}

// ---------------- FP16 TC GEMM body, 128x128 tile, K-stage 64, dbl buffer --
#define HLD 72
#define GSTAGE (128 * HLD)
template<int MODE>
__device__ __forceinline__ void gemm_body(__half* As, __half* Bs,
                        const __half* __restrict__ A, const __half* __restrict__ Bt,
                        const float* __restrict__ bias, float* __restrict__ C,
                        int M, int N, int K, int bxx, int byy) {
    int tid  = threadIdx.x, lane = tid & 31, warp = tid >> 5;
    int wm = warp >> 2, wn = warp & 3;     // 2 x 4, warp tile 64x32
    int g  = lane >> 2, t4 = lane & 3;
    int bm = byy * 128, bn = bxx * 128;

    float c[4][4][4];
    #pragma unroll
    for (int mt = 0; mt < 4; mt++)
        #pragma unroll
        for (int nt = 0; nt < 4; nt++)
            #pragma unroll
            for (int i = 0; i < 4; i++) c[mt][nt][i] = 0.f;

    int nstg = K >> 6;   // K/64
    int ldr = tid >> 1, ldc = (tid & 1) << 5;   // 128 rows x 2 half-chunks(32)
    {
        const __half* a0 = A  + (size_t)(bm + ldr) * K + ldc;
        const __half* b0 = Bt + (size_t)(bn + ldr) * K + ldc;
        __half* da = As + ldr * HLD + ldc;
        __half* db = Bs + ldr * HLD + ldc;
        cpa16(da, a0); cpa16(da + 8, a0 + 8); cpa16(da + 16, a0 + 16); cpa16(da + 24, a0 + 24);
        cpa16(db, b0); cpa16(db + 8, b0 + 8); cpa16(db + 16, b0 + 16); cpa16(db + 24, b0 + 24);
        CP_COMMIT;
    }
    for (int s = 0; s < nstg; s++) {
        CP_WAIT0; __syncthreads();
        if (s + 1 < nstg) {
            int buf = (s + 1) & 1, k0 = (s + 1) << 6;
            const __half* a0 = A  + (size_t)(bm + ldr) * K + k0 + ldc;
            const __half* b0 = Bt + (size_t)(bn + ldr) * K + k0 + ldc;
            __half* da = As + buf * GSTAGE + ldr * HLD + ldc;
            __half* db = Bs + buf * GSTAGE + ldr * HLD + ldc;
            cpa16(da, a0); cpa16(da + 8, a0 + 8); cpa16(da + 16, a0 + 16); cpa16(da + 24, a0 + 24);
            cpa16(db, b0); cpa16(db + 8, b0 + 8); cpa16(db + 16, b0 + 16); cpa16(db + 24, b0 + 24);
            CP_COMMIT;
        }
        const __half* Ab = As + (s & 1) * GSTAGE;
        const __half* Bb = Bs + (s & 1) * GSTAGE;
        #pragma unroll
        for (int kk = 0; kk < 64; kk += 16) {
            unsigned a[4][4], b[4][2];
            #pragma unroll
            for (int mt = 0; mt < 4; mt++) {
                const __half* ap = Ab + (wm*64 + mt*16 + g) * HLD + kk + 2*t4;
                a[mt][0] = *(const unsigned*)(ap);
                a[mt][1] = *(const unsigned*)(ap + 8 * HLD);
                a[mt][2] = *(const unsigned*)(ap + 8);
                a[mt][3] = *(const unsigned*)(ap + 8 * HLD + 8);
            }
            #pragma unroll
            for (int nt = 0; nt < 4; nt++) {
                const __half* bp = Bb + (wn*32 + nt*8 + g) * HLD + kk + 2*t4;
                b[nt][0] = *(const unsigned*)(bp);
                b[nt][1] = *(const unsigned*)(bp + 8);
            }
            #pragma unroll
            for (int mt = 0; mt < 4; mt++)
                #pragma unroll
                for (int nt = 0; nt < 4; nt++)
                    mma_f16(c[mt][nt], a[mt], b[nt]);
        }
        __syncthreads();
    }

    // epilogue
    #pragma unroll
    for (int mt = 0; mt < 4; mt++) {
        #pragma unroll
        for (int nt = 0; nt < 4; nt++) {
            int r0 = bm + wm*64 + mt*16 + g;
            int c0 = bn + wn*32 + nt*8 + t4*2;
            #pragma unroll
            for (int e = 0; e < 4; e++) {
                int r = r0 + ((e >> 1) ? 8 : 0);
                int cc = c0 + (e & 1);
                float val = c[mt][nt][e] + (bias ? bias[cc] : 0.f);
                if (MODE == 0) {
                    C[(size_t)r * N + cc] = val;            // final output: fp32
                } else if (MODE == 1) {
                    int which = cc >> 9, rem = cc & 511;
                    int h = rem >> 6, dh = rem & 63;
                    int b_ = r >> 10, l = r & 1023;
                    __half hv = __float2half_rn(val);
                    if (which == 0)
                        g_q[(((size_t)b_ * HH + h) * LL + l) * DH + dh] = hv;
                    else if (which == 1)
                        g_k[(((size_t)b_ * HH + h) * LL + l) * DH + dh] = hv;
                    else  // V transposed: [bh][dh][l]
                        g_v[(((size_t)b_ * HH + h) * DH + dh) * LL + l] = hv;
                } else {
                    int h = cc >> 6, dh = cc & 63;
                    g_pos[((size_t)h * LL + r) * DH + dh] = __float2half_rn(val);
                }
            }
        }
    }
}

__global__ __launch_bounds__(256, 2) void gemm_fused(const float* __restrict__ b_qkv) {
    __shared__ __half As[2 * GSTAGE];
    __shared__ __half Bs[2 * GSTAGE];
    if (blockIdx.z == 0) {
        gemm_body<1>(As, Bs, g_xn, g_wqkv, b_qkv, nullptr, ROWS, 3*INNER, DD,
                     blockIdx.x, blockIdx.y);
    } else {
        if (blockIdx.x >= INNER/128 || blockIdx.y >= LL/128) return;
        gemm_body<2>(As, Bs, g_pe, g_wpos, nullptr, nullptr, LL, INNER, DD,
                     blockIdx.x, blockIdx.y);
    }
}

__global__ __launch_bounds__(256, 2) void gemm_out(const float* __restrict__ b_out,
                                                   float* __restrict__ out) {
    __shared__ __half As[2 * GSTAGE];
    __shared__ __half Bs[2 * GSTAGE];
    gemm_body<0>(As, Bs, g_att, g_wout, b_out, out, ROWS, DD, INNER,
                 blockIdx.x, blockIdx.y);
}

// ---------------- flash attention: register-resident softmax ----------------
// Q-tile 128 rows, KV-tile 64 keys, 256 thr, 8 warps; warp w owns rows
// [w*16, w*16+16) x ALL 64 key cols (8 n-tiles). Softmax per-row in registers
// (shfl over t4 quad); score C-frags convert in-register to AV A-frags.
#define ATL  136   // sA / sKP row stride (halves)
#define VTL  72    // sVT row stride (halves)
#define N_SA  (128 * ATL)
#define N_SKP (2 * 64 * ATL)
#define N_SVT (2 * 64 * VTL)
#define ATT_SMEM_BYTES ((N_SA + N_SKP + N_SVT) * 2)   // ~86 KB

__global__ __launch_bounds__(256, 2) void attn_tc(const float* __restrict__ u_bias,
                                                  const float* __restrict__ v_bias) {
    extern __shared__ char smbase[];
    __half* sA  = (__half*)smbase;
    __half* sKP = sA  + N_SA;
    __half* sVT = sKP + N_SKP;

    int tid = threadIdx.x, lane = tid & 31, warp = tid >> 5;
    int g  = lane >> 2, t4 = lane & 3;
    int wr = warp * 16;                      // warp's row base in q tile
    int bh = blockIdx.y, b = bh >> 3, h = bh & 7;
    int q0 = blockIdx.x * 128;

    const __half* qb  = g_q   + (size_t)bh * LL * DH;
    const __half* kb  = g_k   + (size_t)bh * LL * DH;
    const __half* vtb = g_v   + (size_t)bh * DH * LL;   // [dh][l]
    const __half* pb  = g_pos + (size_t)h  * LL * DH;

    // prologue: stage 0 of K|P and V^T
    for (int idx = tid; idx < 512; idx += 256) {
        int m = idx >> 3, c8 = (idx & 7) << 3;
        cpa16(sKP + m * ATL + c8,      kb  + (size_t)m * DH + c8);
        cpa16(sKP + m * ATL + 64 + c8, pb  + (size_t)m * DH + c8);
        cpa16(sVT + m * VTL + c8,      vtb + (size_t)m * LL + c8);   // m = dh row
    }
    CP_COMMIT;

    // build sA = [Q+u | Q+v] (half)
    for (int idx = tid; idx < 4096; idx += 256) {
        int r = idx >> 5, c2 = idx & 31;
        float2 qf = __half22float2(*(const __half2*)(qb + (size_t)(q0 + r) * DH + 2*c2));
        float2 uf = *(const float2*)(u_bias + h * DH + 2*c2);
        float2 vf = *(const float2*)(v_bias + h * DH + 2*c2);
        *(__half2*)(sA + r * ATL + 2*c2)      = __floats2half2_rn(qf.x + uf.x, qf.y + uf.y);
        *(__half2*)(sA + r * ATL + 64 + 2*c2) = __floats2half2_rn(qf.x + vf.x, qf.y + vf.y);
    }

    float mi0 = -INFINITY, mi1 = -INFINITY, li0 = 0.f, li1 = 0.f;
    float o[8][4];
    #pragma unroll
    for (int nt = 0; nt < 8; nt++)
        #pragma unroll
        for (int i = 0; i < 4; i++) o[nt][i] = 0.f;

    for (int kt = 0; kt < LL / 64; kt++) {
        CP_WAIT0;
        __syncthreads();
        int cur = kt & 1;
        if (kt + 1 < LL / 64) {
            int nb = (kt + 1) & 1;
            __half* dKP = sKP + nb * 64 * ATL;
            __half* dVT = sVT + nb * 64 * VTL;
            int kbase = (kt + 1) * 64;
            for (int idx = tid; idx < 512; idx += 256) {
                int m = idx >> 3, c8 = (idx & 7) << 3;
                cpa16(dKP + m * ATL + c8,      kb  + (size_t)(kbase + m) * DH + c8);
                cpa16(dKP + m * ATL + 64 + c8, pb  + (size_t)(kbase + m) * DH + c8);
                cpa16(dVT + m * VTL + c8,      vtb + (size_t)m * LL + kbase + c8);
            }
            CP_COMMIT;
        }
        const __half* KPb = sKP + cur * 64 * ATL;
        const __half* VTb = sVT + cur * 64 * VTL;

        // scores: warp tile 16(m) x 64(n), K=128 (8 k16 steps, 8 n-tiles)
        float s[8][4];
        #pragma unroll
        for (int nt = 0; nt < 8; nt++)
            #pragma unroll
            for (int i = 0; i < 4; i++) s[nt][i] = 0.f;
        #pragma unroll
        for (int kk = 0; kk < 128; kk += 16) {
            unsigned a[4];
            const __half* ap = sA + (wr + g) * ATL + kk + 2*t4;
            a[0] = *(const unsigned*)(ap);
            a[1] = *(const unsigned*)(ap + 8 * ATL);
            a[2] = *(const unsigned*)(ap + 8);
            a[3] = *(const unsigned*)(ap + 8 * ATL + 8);
            #pragma unroll
            for (int nt = 0; nt < 8; nt++) {
                unsigned bf[2];
                const __half* bp = KPb + (nt*8 + g) * ATL + kk + 2*t4;
                bf[0] = *(const unsigned*)(bp);
                bf[1] = *(const unsigned*)(bp + 8);
                mma_f16(s[nt], a, bf);
            }
        }

        // register softmax: rows r0 = wr+g (elems 0,1), r1 = wr+g+8 (elems 2,3)
        float m0 = -INFINITY, m1 = -INFINITY;
        #pragma unroll
        for (int nt = 0; nt < 8; nt++) {
            s[nt][0] *= 0.125f; s[nt][1] *= 0.125f;
            s[nt][2] *= 0.125f; s[nt][3] *= 0.125f;
            m0 = fmaxf(m0, fmaxf(s[nt][0], s[nt][1]));
            m1 = fmaxf(m1, fmaxf(s[nt][2], s[nt][3]));
        }
        m0 = fmaxf(m0, __shfl_xor_sync(0xffffffffu, m0, 1));
        m0 = fmaxf(m0, __shfl_xor_sync(0xffffffffu, m0, 2));
        m1 = fmaxf(m1, __shfl_xor_sync(0xffffffffu, m1, 1));
        m1 = fmaxf(m1, __shfl_xor_sync(0xffffffffu, m1, 2));
        float newm0 = fmaxf(mi0, m0), newm1 = fmaxf(mi1, m1);
        float alpha0 = __expf(mi0 - newm0), alpha1 = __expf(mi1 - newm1);
        mi0 = newm0; mi1 = newm1;
        float ls0 = 0.f, ls1 = 0.f;
        unsigned pa[4][4];
        #pragma unroll
        for (int nt = 0; nt < 8; nt++) {
            float p0 = __expf(s[nt][0] - newm0);
            float p1 = __expf(s[nt][1] - newm0);
            float p2 = __expf(s[nt][2] - newm1);
            float p3 = __expf(s[nt][3] - newm1);
            ls0 += p0 + p1; ls1 += p2 + p3;
            unsigned lo = pack_h2(p0, p1);
            unsigned hi = pack_h2(p2, p3);
            // n-tile nt covers score cols nt*8.. -> AV k-chunk nt>>1, frag slot (nt&1)
            pa[nt >> 1][(nt & 1) ? 2 : 0] = lo;
            pa[nt >> 1][(nt & 1) ? 3 : 1] = hi;
        }
        li0 = li0 * alpha0 + ls0;
        li1 = li1 * alpha1 + ls1;

        // rescale O, then AV: O += P.V  (K=64: 4 k16 chunks; 8 dh n-tiles)
        #pragma unroll
        for (int nt = 0; nt < 8; nt++) {
            o[nt][0] *= alpha0; o[nt][1] *= alpha0;
            o[nt][2] *= alpha1; o[nt][3] *= alpha1;
        }
        #pragma unroll
        for (int kc = 0; kc < 4; kc++) {
            #pragma unroll
            for (int nt = 0; nt < 8; nt++) {
                unsigned bf[2];
                const __half* bp = VTb + (nt*8 + g) * VTL + kc*16 + 2*t4;
                bf[0] = *(const unsigned*)(bp);
                bf[1] = *(const unsigned*)(bp + 8);
                mma_f16(o[nt], pa[kc], bf);
            }
        }
    }

    // finalize: reduce li over t4 quad, write g_att (half)
    li0 += __shfl_xor_sync(0xffffffffu, li0, 1);
    li0 += __shfl_xor_sync(0xffffffffu, li0, 2);
    li1 += __shfl_xor_sync(0xffffffffu, li1, 1);
    li1 += __shfl_xor_sync(0xffffffffu, li1, 2);
    float inv0 = 1.f / li0, inv1 = 1.f / li1;
    int r0 = wr + g;
    __half* ob1 = g_att + ((size_t)(b * LL + q0 + r0))     * INNER + h * DH;
    __half* ob2 = g_att + ((size_t)(b * LL + q0 + r0 + 8)) * INNER + h * DH;
    #pragma unroll
    for (int nt = 0; nt < 8; nt++) {
        int dh0 = nt*8 + t4*2;
        *(__half2*)(ob1 + dh0) = __floats2half2_rn(o[nt][0] * inv0, o[nt][1] * inv0);
        *(__half2*)(ob2 + dh0) = __floats2half2_rn(o[nt][2] * inv1, o[nt][3] * inv1);
    }
}

// ---------------- launch ----------------
extern "C" void kernel_launch(void* const* d_in, const int* in_sizes, int n_in,
                              void* d_out, int out_size) {
    const float* x      = (const float*)d_in[0];
    const float* gamma  = (const float*)d_in[1];
    const float* beta   = (const float*)d_in[2];
    const float* w_qkv  = (const float*)d_in[3];
    const float* b_qkv  = (const float*)d_in[4];
    const float* w_pos  = (const float*)d_in[5];
    const float* w_out  = (const float*)d_in[6];
    const float* b_out  = (const float*)d_in[7];
    const float* u_bias = (const float*)d_in[8];
    const float* v_bias = (const float*)d_in[9];
    float* out = (float*)d_out;

    // 1. convert weights to half + freq table (independent, tiny)
    {
        int n4 = (3*INNER*DD + INNER*DD + DD*INNER) / 4;
        cvt_w<<<(n4 + 255) / 256, 256>>>(w_qkv, w_pos, w_out);
        freq_kernel<<<2, 256>>>();
    }

    // 2. fused LayerNorm + PE table
    ln_pe_kernel<<<ROWS + (LL*DD)/256, 256>>>(x, gamma, beta);

    // 3. fused QKV GEMM + pos GEMM
    {
        dim3 grid((3 * INNER) / 128, ROWS / 128, 2);
        gemm_fused<<<grid, 256>>>(b_qkv);
    }

    // 4. attention
    {
        int smem = ATT_SMEM_BYTES;   // ~86 KB
        cudaFuncSetAttribute(attn_tc, cudaFuncAttributeMaxDynamicSharedMemorySize, smem);
        dim3 grid(LL / 128, BB * HH);
        attn_tc<<<grid, 256, smem>>>(u_bias, v_bias);
    }

    // 5. out projection -> d_out
    {
        dim3 grid(DD / 128, ROWS / 128);
        gemm_out<<<grid, 256>>>(b_out, out);
    }
}

// round 11
// speedup vs baseline: 2.3074x; 1.0861x over previous
#include <cuda_runtime.h>
#include <cuda_fp16.h>
#include <math.h>

// Problem constants
#define BB 8
#define LL 1024
#define DD 512
#define HH 8
#define DH 64
#define INNER 512
#define ROWS (BB*LL)          // 8192
#define EPSV 1e-5f

// ---------------- scratch (device globals; no allocation) ----------------
__device__ __half  g_xn [ROWS*DD];
__device__ __half  g_pe [LL*DD];
__device__ __half  g_pos[HH*LL*DH];
__device__ __half  g_q  [BB*HH*LL*DH];
__device__ __half  g_k  [BB*HH*LL*DH];
__device__ __half  g_v  [BB*HH*DH*LL];     // TRANSPOSED: [bh][dh][l]
__device__ __half  g_att[ROWS*INNER];
__device__ __half  g_wqkv[3*INNER*DD];
__device__ __half  g_wpos[INNER*DD];
__device__ __half  g_wout[DD*INNER];
__device__ double  g_freq[DD];

// ---------------- helpers ----------------
__device__ __forceinline__ void mma_f16(float c[4], const unsigned a[4], const unsigned b[2]) {
    asm volatile(
        "mma.sync.aligned.m16n8k16.row.col.f32.f16.f16.f32 "
        "{%0,%1,%2,%3}, {%4,%5,%6,%7}, {%8,%9}, {%0,%1,%2,%3};"
        : "+f"(c[0]), "+f"(c[1]), "+f"(c[2]), "+f"(c[3])
        : "r"(a[0]), "r"(a[1]), "r"(a[2]), "r"(a[3]), "r"(b[0]), "r"(b[1]));
}

// ldmatrix x4: 4 8x8 b16 matrices; per-lane address selects a 16B row
__device__ __forceinline__ void ldsm4(unsigned r[4], const __half* p) {
    unsigned addr = (unsigned)__cvta_generic_to_shared((void*)p);
    asm volatile("ldmatrix.sync.aligned.m8n8.x4.shared.b16 {%0,%1,%2,%3}, [%4];"
        : "=r"(r[0]), "=r"(r[1]), "=r"(r[2]), "=r"(r[3]) : "r"(addr));
}

// pack two fp32 into one f16x2 register (lo = x, hi = y)
__device__ __forceinline__ unsigned pack_h2(float x, float y) {
    unsigned r;
    asm("cvt.rn.f16x2.f32 %0, %1, %2;" : "=r"(r) : "f"(y), "f"(x));
    return r;
}

__device__ __forceinline__ void cpa16(void* dst_smem, const void* src) {
    unsigned d = (unsigned)__cvta_generic_to_shared(dst_smem);
    asm volatile("cp.async.cg.shared.global [%0], [%1], 16;" :: "r"(d), "l"(src));
}
#define CP_COMMIT asm volatile("cp.async.commit_group;")
#define CP_WAIT0  asm volatile("cp.async.wait_group 0;")

// ---------------- convert weights to half + freq table (one launch) -------
__global__ void cvt_w(const float* __restrict__ wq, const float* __restrict__ wp,
                      const float* __restrict__ wo) {
    const int n1 = 3*INNER*DD/4, n2 = INNER*DD/4, n3 = DD*INNER/4;
    int i = blockIdx.x * blockDim.x + threadIdx.x;
    if (i < DD) g_freq[i] = exp(-(double)i * (log(10000.0) / 256.0));
    float4 v; __half* dst;
    if (i < n1) {
        v = ((const float4*)wq)[i]; dst = g_wqkv + 4*i;
    } else if (i < n1 + n2) {
        v = ((const float4*)wp)[i - n1]; dst = g_wpos + 4*(i - n1);
    } else if (i < n1 + n2 + n3) {
        v = ((const float4*)wo)[i - n1 - n2]; dst = g_wout + 4*(i - n1 - n2);
    } else return;
    *(__half2*)(dst)     = __floats2half2_rn(v.x, v.y);
    *(__half2*)(dst + 2) = __floats2half2_rn(v.z, v.w);
}

// ---------------- fused LayerNorm (warp per row) + PE table ----------------
__global__ void ln_pe_kernel(const float* __restrict__ x,
                             const float* __restrict__ gamma,
                             const float* __restrict__ beta) {
    int tid = threadIdx.x, lane = tid & 31, warp = tid >> 5;
    if (blockIdx.x < ROWS / 8) {
        int row = blockIdx.x * 8 + warp;
        const float* xr = x + (size_t)row * DD;
        float4 v[4];
        float s = 0.f, sq = 0.f;
        #pragma unroll
        for (int k = 0; k < 4; k++) {
            v[k] = *(const float4*)(xr + k * 128 + lane * 4);
            s  += v[k].x + v[k].y + v[k].z + v[k].w;
            sq += v[k].x*v[k].x + v[k].y*v[k].y + v[k].z*v[k].z + v[k].w*v[k].w;
        }
        #pragma unroll
        for (int o = 16; o; o >>= 1) {
            s  += __shfl_xor_sync(0xffffffffu, s,  o);
            sq += __shfl_xor_sync(0xffffffffu, sq, o);
        }
        float mu  = s * (1.f / DD);
        float var = fmaxf(sq * (1.f / DD) - mu * mu, 0.f);
        float rs  = rsqrtf(var + EPSV);
        __half* o = g_xn + (size_t)row * DD;
        #pragma unroll
        for (int k = 0; k < 4; k++) {
            int c = k * 128 + lane * 4;
            float4 gm = *(const float4*)(gamma + c);
            float4 bt = *(const float4*)(beta + c);
            *(__half2*)(o + c)     = __floats2half2_rn((v[k].x - mu)*rs*gm.x + bt.x,
                                                       (v[k].y - mu)*rs*gm.y + bt.y);
            *(__half2*)(o + c + 2) = __floats2half2_rn((v[k].z - mu)*rs*gm.z + bt.z,
                                                       (v[k].w - mu)*rs*gm.w + bt.w);
        }
    } else {
        int idx = (blockIdx.x - ROWS / 8) * 256 + tid;
        if (idx >= LL * DD) return;
        int i = idx >> 9;
        int j = idx & 511;
        double angle = (double)(i - j) * g_freq[j];
        double n = rint(angle * 0.15915494309189535);   // 1/(2*pi)
        double r = angle - n * 6.283185307179586;       // reduced to [-pi, pi]
        float rf = (float)r;
        g_pe[idx] = __float2half_rn(((j & 1) == 0) ? cosf(rf) : sinf(rf));
    }
}

// ---------------- FP16 TC GEMM body, 128x128 tile, K-stage 64, dbl buffer --
#define HLD 72
#define GSTAGE (128 * HLD)
template<int MODE>
__device__ __forceinline__ void gemm_body(__half* As, __half* Bs,
                        const __half* __restrict__ A, const __half* __restrict__ Bt,
                        const float* __restrict__ bias, float* __restrict__ C,
                        int M, int N, int K, int bxx, int byy) {
    int tid  = threadIdx.x, lane = tid & 31, warp = tid >> 5;
    int wm = warp >> 2, wn = warp & 3;     // 2 x 4, warp tile 64x32
    int g  = lane >> 2, t4 = lane & 3;
    int bm = byy * 128, bn = bxx * 128;
    // LDSM per-lane addressing
    int l15 = lane & 15, lh = (lane >> 4) << 3;                 // A: row, k-half
    int bn8 = lane & 7, bkh = ((lane >> 3) & 1) << 3, bnp = (lane >> 4) << 3; // B

    float c[4][4][4];
    #pragma unroll
    for (int mt = 0; mt < 4; mt++)
        #pragma unroll
        for (int nt = 0; nt < 4; nt++)
            #pragma unroll
            for (int i = 0; i < 4; i++) c[mt][nt][i] = 0.f;

    int nstg = K >> 6;   // K/64
    int ldr = tid >> 1, ldc = (tid & 1) << 5;   // 128 rows x 2 half-chunks(32)
    {
        const __half* a0 = A  + (size_t)(bm + ldr) * K + ldc;
        const __half* b0 = Bt + (size_t)(bn + ldr) * K + ldc;
        __half* da = As + ldr * HLD + ldc;
        __half* db = Bs + ldr * HLD + ldc;
        cpa16(da, a0); cpa16(da + 8, a0 + 8); cpa16(da + 16, a0 + 16); cpa16(da + 24, a0 + 24);
        cpa16(db, b0); cpa16(db + 8, b0 + 8); cpa16(db + 16, b0 + 16); cpa16(db + 24, b0 + 24);
        CP_COMMIT;
    }
    for (int s = 0; s < nstg; s++) {
        CP_WAIT0; __syncthreads();
        if (s + 1 < nstg) {
            int buf = (s + 1) & 1, k0 = (s + 1) << 6;
            const __half* a0 = A  + (size_t)(bm + ldr) * K + k0 + ldc;
            const __half* b0 = Bt + (size_t)(bn + ldr) * K + k0 + ldc;
            __half* da = As + buf * GSTAGE + ldr * HLD + ldc;
            __half* db = Bs + buf * GSTAGE + ldr * HLD + ldc;
            cpa16(da, a0); cpa16(da + 8, a0 + 8); cpa16(da + 16, a0 + 16); cpa16(da + 24, a0 + 24);
            cpa16(db, b0); cpa16(db + 8, b0 + 8); cpa16(db + 16, b0 + 16); cpa16(db + 24, b0 + 24);
            CP_COMMIT;
        }
        const __half* Ab = As + (s & 1) * GSTAGE;
        const __half* Bb = Bs + (s & 1) * GSTAGE;
        #pragma unroll
        for (int kk = 0; kk < 64; kk += 16) {
            unsigned a[4][4], b01[4], b23[4];
            #pragma unroll
            for (int mt = 0; mt < 4; mt++)
                ldsm4(a[mt], Ab + (wm*64 + mt*16 + l15) * HLD + kk + lh);
            ldsm4(b01, Bb + (wn*32 +      bnp + bn8) * HLD + kk + bkh);
            ldsm4(b23, Bb + (wn*32 + 16 + bnp + bn8) * HLD + kk + bkh);
            #pragma unroll
            for (int mt = 0; mt < 4; mt++) {
                mma_f16(c[mt][0], a[mt], &b01[0]);
                mma_f16(c[mt][1], a[mt], &b01[2]);
                mma_f16(c[mt][2], a[mt], &b23[0]);
                mma_f16(c[mt][3], a[mt], &b23[2]);
            }
        }
        __syncthreads();
    }

    // epilogue
    #pragma unroll
    for (int mt = 0; mt < 4; mt++) {
        #pragma unroll
        for (int nt = 0; nt < 4; nt++) {
            int r0 = bm + wm*64 + mt*16 + g;
            int c0 = bn + wn*32 + nt*8 + t4*2;
            #pragma unroll
            for (int e = 0; e < 4; e++) {
                int r = r0 + ((e >> 1) ? 8 : 0);
                int cc = c0 + (e & 1);
                float val = c[mt][nt][e] + (bias ? bias[cc] : 0.f);
                if (MODE == 0) {
                    C[(size_t)r * N + cc] = val;            // final output: fp32
                } else if (MODE == 1) {
                    int which = cc >> 9, rem = cc & 511;
                    int h = rem >> 6, dh = rem & 63;
                    int b_ = r >> 10, l = r & 1023;
                    __half hv = __float2half_rn(val);
                    if (which == 0)
                        g_q[(((size_t)b_ * HH + h) * LL + l) * DH + dh] = hv;
                    else if (which == 1)
                        g_k[(((size_t)b_ * HH + h) * LL + l) * DH + dh] = hv;
                    else  // V transposed: [bh][dh][l]
                        g_v[(((size_t)b_ * HH + h) * DH + dh) * LL + l] = hv;
                } else {
                    int h = cc >> 6, dh = cc & 63;
                    g_pos[((size_t)h * LL + r) * DH + dh] = __float2half_rn(val);
                }
            }
        }
    }
}

__global__ __launch_bounds__(256, 2) void gemm_fused(const float* __restrict__ b_qkv) {
    __shared__ __half As[2 * GSTAGE];
    __shared__ __half Bs[2 * GSTAGE];
    if (blockIdx.z == 0) {
        gemm_body<1>(As, Bs, g_xn, g_wqkv, b_qkv, nullptr, ROWS, 3*INNER, DD,
                     blockIdx.x, blockIdx.y);
    } else {
        if (blockIdx.x >= INNER/128 || blockIdx.y >= LL/128) return;
        gemm_body<2>(As, Bs, g_pe, g_wpos, nullptr, nullptr, LL, INNER, DD,
                     blockIdx.x, blockIdx.y);
    }
}

__global__ __launch_bounds__(256, 2) void gemm_out(const float* __restrict__ b_out,
                                                   float* __restrict__ out) {
    __shared__ __half As[2 * GSTAGE];
    __shared__ __half Bs[2 * GSTAGE];
    gemm_body<0>(As, Bs, g_att, g_wout, b_out, out, ROWS, DD, INNER,
                 blockIdx.x, blockIdx.y);
}

// ---------------- flash attention: register-resident softmax + LDSM --------
#define ATL  136   // sA / sKP row stride (halves)
#define VTL  72    // sVT row stride (halves)
#define N_SA  (128 * ATL)
#define N_SKP (2 * 64 * ATL)
#define N_SVT (2 * 64 * VTL)
#define ATT_SMEM_BYTES ((N_SA + N_SKP + N_SVT) * 2)   // ~86 KB

__global__ __launch_bounds__(256, 2) void attn_tc(const float* __restrict__ u_bias,
                                                  const float* __restrict__ v_bias) {
    extern __shared__ char smbase[];
    __half* sA  = (__half*)smbase;
    __half* sKP = sA  + N_SA;
    __half* sVT = sKP + N_SKP;

    int tid = threadIdx.x, lane = tid & 31, warp = tid >> 5;
    int g  = lane >> 2, t4 = lane & 3;
    int wr = warp * 16;                      // warp's row base in q tile
    int bh = blockIdx.y, b = bh >> 3, h = bh & 7;
    int q0 = blockIdx.x * 128;
    // LDSM per-lane addressing
    int l15 = lane & 15, lh = (lane >> 4) << 3;
    int bn8 = lane & 7, bkh = ((lane >> 3) & 1) << 3, bnp = (lane >> 4) << 3;

    const __half* qb  = g_q   + (size_t)bh * LL * DH;
    const __half* kb  = g_k   + (size_t)bh * LL * DH;
    const __half* vtb = g_v   + (size_t)bh * DH * LL;   // [dh][l]
    const __half* pb  = g_pos + (size_t)h  * LL * DH;

    // prologue: stage 0 of K|P and V^T
    for (int idx = tid; idx < 512; idx += 256) {
        int m = idx >> 3, c8 = (idx & 7) << 3;
        cpa16(sKP + m * ATL + c8,      kb  + (size_t)m * DH + c8);
        cpa16(sKP + m * ATL + 64 + c8, pb  + (size_t)m * DH + c8);
        cpa16(sVT + m * VTL + c8,      vtb + (size_t)m * LL + c8);   // m = dh row
    }
    CP_COMMIT;

    // build sA = [Q+u | Q+v] (half)
    for (int idx = tid; idx < 4096; idx += 256) {
        int r = idx >> 5, c2 = idx & 31;
        float2 qf = __half22float2(*(const __half2*)(qb + (size_t)(q0 + r) * DH + 2*c2));
        float2 uf = *(const float2*)(u_bias + h * DH + 2*c2);
        float2 vf = *(const float2*)(v_bias + h * DH + 2*c2);
        *(__half2*)(sA + r * ATL + 2*c2)      = __floats2half2_rn(qf.x + uf.x, qf.y + uf.y);
        *(__half2*)(sA + r * ATL + 64 + 2*c2) = __floats2half2_rn(qf.x + vf.x, qf.y + vf.y);
    }

    float mi0 = -INFINITY, mi1 = -INFINITY, li0 = 0.f, li1 = 0.f;
    float o[8][4];
    #pragma unroll
    for (int nt = 0; nt < 8; nt++)
        #pragma unroll
        for (int i = 0; i < 4; i++) o[nt][i] = 0.f;

    for (int kt = 0; kt < LL / 64; kt++) {
        CP_WAIT0;
        __syncthreads();
        int cur = kt & 1;
        if (kt + 1 < LL / 64) {
            int nb = (kt + 1) & 1;
            __half* dKP = sKP + nb * 64 * ATL;
            __half* dVT = sVT + nb * 64 * VTL;
            int kbase = (kt + 1) * 64;
            for (int idx = tid; idx < 512; idx += 256) {
                int m = idx >> 3, c8 = (idx & 7) << 3;
                cpa16(dKP + m * ATL + c8,      kb  + (size_t)(kbase + m) * DH + c8);
                cpa16(dKP + m * ATL + 64 + c8, pb  + (size_t)(kbase + m) * DH + c8);
                cpa16(dVT + m * VTL + c8,      vtb + (size_t)m * LL + kbase + c8);
            }
            CP_COMMIT;
        }
        const __half* KPb = sKP + cur * 64 * ATL;
        const __half* VTb = sVT + cur * 64 * VTL;

        // scores: warp tile 16(m) x 64(n), K=128 (8 k16 steps, 4 LDSM pairs)
        float s[8][4];
        #pragma unroll
        for (int nt = 0; nt < 8; nt++)
            #pragma unroll
            for (int i = 0; i < 4; i++) s[nt][i] = 0.f;
        #pragma unroll
        for (int kk = 0; kk < 128; kk += 16) {
            unsigned a[4];
            ldsm4(a, sA + (wr + l15) * ATL + kk + lh);
            #pragma unroll
            for (int pr = 0; pr < 4; pr++) {
                unsigned bb[4];
                ldsm4(bb, KPb + (pr*16 + bnp + bn8) * ATL + kk + bkh);
                mma_f16(s[2*pr],     a, &bb[0]);
                mma_f16(s[2*pr + 1], a, &bb[2]);
            }
        }

        // register softmax: rows r0 = wr+g (elems 0,1), r1 = wr+g+8 (elems 2,3)
        float m0 = -INFINITY, m1 = -INFINITY;
        #pragma unroll
        for (int nt = 0; nt < 8; nt++) {
            s[nt][0] *= 0.125f; s[nt][1] *= 0.125f;
            s[nt][2] *= 0.125f; s[nt][3] *= 0.125f;
            m0 = fmaxf(m0, fmaxf(s[nt][0], s[nt][1]));
            m1 = fmaxf(m1, fmaxf(s[nt][2], s[nt][3]));
        }
        m0 = fmaxf(m0, __shfl_xor_sync(0xffffffffu, m0, 1));
        m0 = fmaxf(m0, __shfl_xor_sync(0xffffffffu, m0, 2));
        m1 = fmaxf(m1, __shfl_xor_sync(0xffffffffu, m1, 1));
        m1 = fmaxf(m1, __shfl_xor_sync(0xffffffffu, m1, 2));
        float newm0 = fmaxf(mi0, m0), newm1 = fmaxf(mi1, m1);
        float alpha0 = __expf(mi0 - newm0), alpha1 = __expf(mi1 - newm1);
        mi0 = newm0; mi1 = newm1;
        float ls0 = 0.f, ls1 = 0.f;
        unsigned pa[4][4];
        #pragma unroll
        for (int nt = 0; nt < 8; nt++) {
            float p0 = __expf(s[nt][0] - newm0);
            float p1 = __expf(s[nt][1] - newm0);
            float p2 = __expf(s[nt][2] - newm1);
            float p3 = __expf(s[nt][3] - newm1);
            ls0 += p0 + p1; ls1 += p2 + p3;
            unsigned lo = pack_h2(p0, p1);
            unsigned hi = pack_h2(p2, p3);
            // n-tile nt covers score cols nt*8.. -> AV k-chunk nt>>1, frag slot (nt&1)
            pa[nt >> 1][(nt & 1) ? 2 : 0] = lo;
            pa[nt >> 1][(nt & 1) ? 3 : 1] = hi;
        }
        li0 = li0 * alpha0 + ls0;
        li1 = li1 * alpha1 + ls1;

        // rescale O, then AV: O += P.V  (K=64: 4 k16 chunks; 4 LDSM pairs)
        #pragma unroll
        for (int nt = 0; nt < 8; nt++) {
            o[nt][0] *= alpha0; o[nt][1] *= alpha0;
            o[nt][2] *= alpha1; o[nt][3] *= alpha1;
        }
        #pragma unroll
        for (int kc = 0; kc < 4; kc++) {
            #pragma unroll
            for (int pr = 0; pr < 4; pr++) {
                unsigned bb[4];
                ldsm4(bb, VTb + (pr*16 + bnp + bn8) * VTL + kc*16 + bkh);
                mma_f16(o[2*pr],     pa[kc], &bb[0]);
                mma_f16(o[2*pr + 1], pa[kc], &bb[2]);
            }
        }
    }

    // finalize: reduce li over t4 quad, write g_att (half)
    li0 += __shfl_xor_sync(0xffffffffu, li0, 1);
    li0 += __shfl_xor_sync(0xffffffffu, li0, 2);
    li1 += __shfl_xor_sync(0xffffffffu, li1, 1);
    li1 += __shfl_xor_sync(0xffffffffu, li1, 2);
    float inv0 = 1.f / li0, inv1 = 1.f / li1;
    int r0 = wr + g;
    __half* ob1 = g_att + ((size_t)(b * LL + q0 + r0))     * INNER + h * DH;
    __half* ob2 = g_att + ((size_t)(b * LL + q0 + r0 + 8)) * INNER + h * DH;
    #pragma unroll
    for (int nt = 0; nt < 8; nt++) {
        int dh0 = nt*8 + t4*2;
        *(__half2*)(ob1 + dh0) = __floats2half2_rn(o[nt][0] * inv0, o[nt][1] * inv0);
        *(__half2*)(ob2 + dh0) = __floats2half2_rn(o[nt][2] * inv1, o[nt][3] * inv1);
    }
}

// ---------------- launch ----------------
extern "C" void kernel_launch(void* const* d_in, const int* in_sizes, int n_in,
                              void* d_out, int out_size) {
    const float* x      = (const float*)d_in[0];
    const float* gamma  = (const float*)d_in[1];
    const float* beta   = (const float*)d_in[2];
    const float* w_qkv  = (const float*)d_in[3];
    const float* b_qkv  = (const float*)d_in[4];
    const float* w_pos  = (const float*)d_in[5];
    const float* w_out  = (const float*)d_in[6];
    const float* b_out  = (const float*)d_in[7];
    const float* u_bias = (const float*)d_in[8];
    const float* v_bias = (const float*)d_in[9];
    float* out = (float*)d_out;

    // 1. convert weights to half + freq table
    {
        int n4 = (3*INNER*DD + INNER*DD + DD*INNER) / 4;
        cvt_w<<<(n4 + 255) / 256, 256>>>(w_qkv, w_pos, w_out);
    }

    // 2. fused LayerNorm (warp/row) + PE table
    ln_pe_kernel<<<ROWS/8 + (LL*DD)/256, 256>>>(x, gamma, beta);

    // 3. fused QKV GEMM + pos GEMM
    {
        dim3 grid((3 * INNER) / 128, ROWS / 128, 2);
        gemm_fused<<<grid, 256>>>(b_qkv);
    }

    // 4. attention
    {
        int smem = ATT_SMEM_BYTES;   // ~86 KB
        cudaFuncSetAttribute(attn_tc, cudaFuncAttributeMaxDynamicSharedMemorySize, smem);
        dim3 grid(LL / 128, BB * HH);
        attn_tc<<<grid, 256, smem>>>(u_bias, v_bias);
    }

    // 5. out projection -> d_out
    {
        dim3 grid(DD / 128, ROWS / 128);
        gemm_out<<<grid, 256>>>(b_out, out);
    }
}

// round 12
// speedup vs baseline: 2.5175x; 1.0911x over previous
#include <cuda_runtime.h>
#include <cuda_fp16.h>
#include <math.h>

// Problem constants
#define BB 8
#define LL 1024
#define DD 512
#define HH 8
#define DH 64
#define INNER 512
#define ROWS (BB*LL)          // 8192
#define EPSV 1e-5f
#define SCALE_LOG2E 0.18033688011112042f   // 0.125 * log2(e)

// ---------------- scratch (device globals; no allocation) ----------------
__device__ __half  g_xn [ROWS*DD];
__device__ __half  g_pe [LL*DD];
__device__ __half  g_pos[HH*LL*DH];
__device__ __half  g_q  [BB*HH*LL*DH];
__device__ __half  g_k  [BB*HH*LL*DH];
__device__ __half  g_v  [BB*HH*DH*LL];     // TRANSPOSED: [bh][dh][l]
__device__ __half  g_att[ROWS*INNER];
__device__ __half  g_wqkv[3*INNER*DD];
__device__ __half  g_wpos[INNER*DD];
__device__ __half  g_wout[DD*INNER];
__device__ double  g_freq[DD];

// ---------------- helpers ----------------
__device__ __forceinline__ void mma_f16(float c[4], const unsigned a[4], const unsigned b[2]) {
    asm volatile(
        "mma.sync.aligned.m16n8k16.row.col.f32.f16.f16.f32 "
        "{%0,%1,%2,%3}, {%4,%5,%6,%7}, {%8,%9}, {%0,%1,%2,%3};"
        : "+f"(c[0]), "+f"(c[1]), "+f"(c[2]), "+f"(c[3])
        : "r"(a[0]), "r"(a[1]), "r"(a[2]), "r"(a[3]), "r"(b[0]), "r"(b[1]));
}

// ldmatrix x4: 4 8x8 b16 matrices; per-lane address selects a 16B row
__device__ __forceinline__ void ldsm4(unsigned r[4], const __half* p) {
    unsigned addr = (unsigned)__cvta_generic_to_shared((void*)p);
    asm volatile("ldmatrix.sync.aligned.m8n8.x4.shared.b16 {%0,%1,%2,%3}, [%4];"
        : "=r"(r[0]), "=r"(r[1]), "=r"(r[2]), "=r"(r[3]) : "r"(addr));
}

// pack two fp32 into one f16x2 register (lo = x, hi = y)
__device__ __forceinline__ unsigned pack_h2(float x, float y) {
    unsigned r;
    asm("cvt.rn.f16x2.f32 %0, %1, %2;" : "=r"(r) : "f"(y), "f"(x));
    return r;
}

// fast 2^x (single MUFU EX2)
__device__ __forceinline__ float ex2(float x) {
    float r;
    asm("ex2.approx.ftz.f32 %0, %1;" : "=f"(r) : "f"(x));
    return r;
}

__device__ __forceinline__ void cpa16(void* dst_smem, const void* src) {
    unsigned d = (unsigned)__cvta_generic_to_shared(dst_smem);
    asm volatile("cp.async.cg.shared.global [%0], [%1], 16;" :: "r"(d), "l"(src));
}
#define CP_COMMIT asm volatile("cp.async.commit_group;")
#define CP_WAIT0  asm volatile("cp.async.wait_group 0;")

// ---------------- convert weights to half + freq table (one launch) -------
__global__ void cvt_w(const float* __restrict__ wq, const float* __restrict__ wp,
                      const float* __restrict__ wo) {
    const int n1 = 3*INNER*DD/4, n2 = INNER*DD/4, n3 = DD*INNER/4;
    int i = blockIdx.x * blockDim.x + threadIdx.x;
    if (i < DD) g_freq[i] = exp(-(double)i * (log(10000.0) / 256.0));
    float4 v; __half* dst;
    if (i < n1) {
        v = ((const float4*)wq)[i]; dst = g_wqkv + 4*i;
    } else if (i < n1 + n2) {
        v = ((const float4*)wp)[i - n1]; dst = g_wpos + 4*(i - n1);
    } else if (i < n1 + n2 + n3) {
        v = ((const float4*)wo)[i - n1 - n2]; dst = g_wout + 4*(i - n1 - n2);
    } else return;
    *(__half2*)(dst)     = __floats2half2_rn(v.x, v.y);
    *(__half2*)(dst + 2) = __floats2half2_rn(v.z, v.w);
}

// ---------------- fused LayerNorm (warp per row) + PE table ----------------
__global__ void ln_pe_kernel(const float* __restrict__ x,
                             const float* __restrict__ gamma,
                             const float* __restrict__ beta) {
    int tid = threadIdx.x, lane = tid & 31, warp = tid >> 5;
    if (blockIdx.x < ROWS / 8) {
        int row = blockIdx.x * 8 + warp;
        const float* xr = x + (size_t)row * DD;
        float4 v[4];
        float s = 0.f, sq = 0.f;
        #pragma unroll
        for (int k = 0; k < 4; k++) {
            v[k] = *(const float4*)(xr + k * 128 + lane * 4);
            s  += v[k].x + v[k].y + v[k].z + v[k].w;
            sq += v[k].x*v[k].x + v[k].y*v[k].y + v[k].z*v[k].z + v[k].w*v[k].w;
        }
        #pragma unroll
        for (int o = 16; o; o >>= 1) {
            s  += __shfl_xor_sync(0xffffffffu, s,  o);
            sq += __shfl_xor_sync(0xffffffffu, sq, o);
        }
        float mu  = s * (1.f / DD);
        float var = fmaxf(sq * (1.f / DD) - mu * mu, 0.f);
        float rs  = rsqrtf(var + EPSV);
        __half* o = g_xn + (size_t)row * DD;
        #pragma unroll
        for (int k = 0; k < 4; k++) {
            int c = k * 128 + lane * 4;
            float4 gm = *(const float4*)(gamma + c);
            float4 bt = *(const float4*)(beta + c);
            *(__half2*)(o + c)     = __floats2half2_rn((v[k].x - mu)*rs*gm.x + bt.x,
                                                       (v[k].y - mu)*rs*gm.y + bt.y);
            *(__half2*)(o + c + 2) = __floats2half2_rn((v[k].z - mu)*rs*gm.z + bt.z,
                                                       (v[k].w - mu)*rs*gm.w + bt.w);
        }
    } else {
        int idx = (blockIdx.x - ROWS / 8) * 256 + tid;
        if (idx >= LL * DD) return;
        int i = idx >> 9;
        int j = idx & 511;
        double angle = (double)(i - j) * g_freq[j];
        double n = rint(angle * 0.15915494309189535);   // 1/(2*pi)
        double r = angle - n * 6.283185307179586;       // reduced to [-pi, pi]
        float rf = (float)r;
        g_pe[idx] = __float2half_rn(((j & 1) == 0) ? cosf(rf) : sinf(rf));
    }
}

// ---------------- FP16 TC GEMM body, 128x128 tile, K-stage 64, dbl buffer --
#define HLD 72
#define GSTAGE (128 * HLD)
template<int MODE>
__device__ __forceinline__ void gemm_body(__half* As, __half* Bs,
                        const __half* __restrict__ A, const __half* __restrict__ Bt,
                        const float* __restrict__ bias, float* __restrict__ C,
                        int M, int N, int K, int bxx, int byy) {
    int tid  = threadIdx.x, lane = tid & 31, warp = tid >> 5;
    int wm = warp >> 2, wn = warp & 3;     // 2 x 4, warp tile 64x32
    int g  = lane >> 2, t4 = lane & 3;
    int bm = byy * 128, bn = bxx * 128;
    // LDSM per-lane addressing
    int l15 = lane & 15, lh = (lane >> 4) << 3;                 // A: row, k-half
    int bn8 = lane & 7, bkh = ((lane >> 3) & 1) << 3, bnp = (lane >> 4) << 3; // B

    float c[4][4][4];
    #pragma unroll
    for (int mt = 0; mt < 4; mt++)
        #pragma unroll
        for (int nt = 0; nt < 4; nt++)
            #pragma unroll
            for (int i = 0; i < 4; i++) c[mt][nt][i] = 0.f;

    int nstg = K >> 6;   // K/64
    int ldr = tid >> 1, ldc = (tid & 1) << 5;   // 128 rows x 2 half-chunks(32)
    {
        const __half* a0 = A  + (size_t)(bm + ldr) * K + ldc;
        const __half* b0 = Bt + (size_t)(bn + ldr) * K + ldc;
        __half* da = As + ldr * HLD + ldc;
        __half* db = Bs + ldr * HLD + ldc;
        cpa16(da, a0); cpa16(da + 8, a0 + 8); cpa16(da + 16, a0 + 16); cpa16(da + 24, a0 + 24);
        cpa16(db, b0); cpa16(db + 8, b0 + 8); cpa16(db + 16, b0 + 16); cpa16(db + 24, b0 + 24);
        CP_COMMIT;
    }
    for (int s = 0; s < nstg; s++) {
        CP_WAIT0; __syncthreads();
        if (s + 1 < nstg) {
            int buf = (s + 1) & 1, k0 = (s + 1) << 6;
            const __half* a0 = A  + (size_t)(bm + ldr) * K + k0 + ldc;
            const __half* b0 = Bt + (size_t)(bn + ldr) * K + k0 + ldc;
            __half* da = As + buf * GSTAGE + ldr * HLD + ldc;
            __half* db = Bs + buf * GSTAGE + ldr * HLD + ldc;
            cpa16(da, a0); cpa16(da + 8, a0 + 8); cpa16(da + 16, a0 + 16); cpa16(da + 24, a0 + 24);
            cpa16(db, b0); cpa16(db + 8, b0 + 8); cpa16(db + 16, b0 + 16); cpa16(db + 24, b0 + 24);
            CP_COMMIT;
        }
        const __half* Ab = As + (s & 1) * GSTAGE;
        const __half* Bb = Bs + (s & 1) * GSTAGE;
        #pragma unroll
        for (int kk = 0; kk < 64; kk += 16) {
            unsigned a[4][4], b01[4], b23[4];
            #pragma unroll
            for (int mt = 0; mt < 4; mt++)
                ldsm4(a[mt], Ab + (wm*64 + mt*16 + l15) * HLD + kk + lh);
            ldsm4(b01, Bb + (wn*32 +      bnp + bn8) * HLD + kk + bkh);
            ldsm4(b23, Bb + (wn*32 + 16 + bnp + bn8) * HLD + kk + bkh);
            #pragma unroll
            for (int mt = 0; mt < 4; mt++) {
                mma_f16(c[mt][0], a[mt], &b01[0]);
                mma_f16(c[mt][1], a[mt], &b01[2]);
                mma_f16(c[mt][2], a[mt], &b23[0]);
                mma_f16(c[mt][3], a[mt], &b23[2]);
            }
        }
        __syncthreads();
    }

    // epilogue (paired stores where destinations are contiguous)
    #pragma unroll
    for (int mt = 0; mt < 4; mt++) {
        #pragma unroll
        for (int nt = 0; nt < 4; nt++) {
            int r0 = bm + wm*64 + mt*16 + g;
            int c0 = bn + wn*32 + nt*8 + t4*2;
            #pragma unroll
            for (int half_ = 0; half_ < 2; half_++) {
                int r = r0 + (half_ ? 8 : 0);
                float v0 = c[mt][nt][2*half_ + 0] + (bias ? bias[c0]     : 0.f);
                float v1 = c[mt][nt][2*half_ + 1] + (bias ? bias[c0 + 1] : 0.f);
                if (MODE == 0) {
                    *(float2*)(C + (size_t)r * N + c0) = make_float2(v0, v1);
                } else if (MODE == 1) {
                    int which = c0 >> 9, rem = c0 & 511;
                    int h = rem >> 6, dh = rem & 63;
                    int b_ = r >> 10, l = r & 1023;
                    if (which == 0)
                        *(__half2*)(g_q + (((size_t)b_ * HH + h) * LL + l) * DH + dh)
                            = __floats2half2_rn(v0, v1);
                    else if (which == 1)
                        *(__half2*)(g_k + (((size_t)b_ * HH + h) * LL + l) * DH + dh)
                            = __floats2half2_rn(v0, v1);
                    else {  // V transposed: [bh][dh][l] — dh not contiguous
                        g_v[(((size_t)b_ * HH + h) * DH + dh)     * LL + l] = __float2half_rn(v0);
                        g_v[(((size_t)b_ * HH + h) * DH + dh + 1) * LL + l] = __float2half_rn(v1);
                    }
                } else {
                    int h = c0 >> 6, dh = c0 & 63;
                    *(__half2*)(g_pos + ((size_t)h * LL + r) * DH + dh)
                        = __floats2half2_rn(v0, v1);
                }
            }
        }
    }
}

__global__ __launch_bounds__(256, 2) void gemm_fused(const float* __restrict__ b_qkv) {
    __shared__ __half As[2 * GSTAGE];
    __shared__ __half Bs[2 * GSTAGE];
    if (blockIdx.z == 0) {
        gemm_body<1>(As, Bs, g_xn, g_wqkv, b_qkv, nullptr, ROWS, 3*INNER, DD,
                     blockIdx.x, blockIdx.y);
    } else {
        if (blockIdx.x >= INNER/128 || blockIdx.y >= LL/128) return;
        gemm_body<2>(As, Bs, g_pe, g_wpos, nullptr, nullptr, LL, INNER, DD,
                     blockIdx.x, blockIdx.y);
    }
}

__global__ __launch_bounds__(256, 2) void gemm_out(const float* __restrict__ b_out,
                                                   float* __restrict__ out) {
    __shared__ __half As[2 * GSTAGE];
    __shared__ __half Bs[2 * GSTAGE];
    gemm_body<0>(As, Bs, g_att, g_wout, b_out, out, ROWS, DD, INNER,
                 blockIdx.x, blockIdx.y);
}

// ---------------- flash attention: log2-unit softmax + ones-column li ------
// Q pre-scaled by 0.125*log2e so scores are in log2 units: p = ex2(s - m).
// V^T buffers extended to 80 rows: row 64 = ones (li via mma), 65..79 = zero.
#define ATL  136   // sA / sKP row stride (halves)
#define VTL  72    // sVT row stride (halves)
#define VTROWS 80  // 64 data + ones row + zero pad (LDSM-safe)
#define N_SA  (128 * ATL)
#define N_SKP (2 * 64 * ATL)
#define N_SVT (2 * VTROWS * VTL)
#define ATT_SMEM_BYTES ((N_SA + N_SKP + N_SVT) * 2)   // ~93 KB

__global__ __launch_bounds__(256, 2) void attn_tc(const float* __restrict__ u_bias,
                                                  const float* __restrict__ v_bias) {
    extern __shared__ char smbase[];
    __half* sA  = (__half*)smbase;
    __half* sKP = sA  + N_SA;
    __half* sVT = sKP + N_SKP;

    int tid = threadIdx.x, lane = tid & 31, warp = tid >> 5;
    int g  = lane >> 2, t4 = lane & 3;
    int wr = warp * 16;                      // warp's row base in q tile
    int bh = blockIdx.y, b = bh >> 3, h = bh & 7;
    int q0 = blockIdx.x * 128;
    // LDSM per-lane addressing
    int l15 = lane & 15, lh = (lane >> 4) << 3;
    int bn8 = lane & 7, bkh = ((lane >> 3) & 1) << 3, bnp = (lane >> 4) << 3;

    const __half* qb  = g_q   + (size_t)bh * LL * DH;
    const __half* kb  = g_k   + (size_t)bh * LL * DH;
    const __half* vtb = g_v   + (size_t)bh * DH * LL;   // [dh][l]
    const __half* pb  = g_pos + (size_t)h  * LL * DH;

    // prologue: stage 0 of K|P and V^T
    for (int idx = tid; idx < 512; idx += 256) {
        int m = idx >> 3, c8 = (idx & 7) << 3;
        cpa16(sKP + m * ATL + c8,      kb  + (size_t)m * DH + c8);
        cpa16(sKP + m * ATL + 64 + c8, pb  + (size_t)m * DH + c8);
        cpa16(sVT + m * VTL + c8,      vtb + (size_t)m * LL + c8);   // m = dh row
    }
    CP_COMMIT;

    // init ones/zero rows (64..79) in BOTH V^T buffers
    {
        __half one = __float2half(1.f), zero = __float2half(0.f);
        for (int idx = tid; idx < 2 * 16 * VTL; idx += 256) {
            int buf = idx / (16 * VTL), rem = idx % (16 * VTL);
            int rrow = rem / VTL, ccol = rem % VTL;
            sVT[buf * VTROWS * VTL + (64 + rrow) * VTL + ccol]
                = (rrow == 0 && ccol < 64) ? one : zero;
        }
    }

    // build sA = (Q+u | Q+v) * 0.125*log2e  (half)
    for (int idx = tid; idx < 4096; idx += 256) {
        int r = idx >> 5, c2 = idx & 31;
        float2 qf = __half22float2(*(const __half2*)(qb + (size_t)(q0 + r) * DH + 2*c2));
        float2 uf = *(const float2*)(u_bias + h * DH + 2*c2);
        float2 vf = *(const float2*)(v_bias + h * DH + 2*c2);
        *(__half2*)(sA + r * ATL + 2*c2)
            = __floats2half2_rn((qf.x + uf.x) * SCALE_LOG2E, (qf.y + uf.y) * SCALE_LOG2E);
        *(__half2*)(sA + r * ATL + 64 + 2*c2)
            = __floats2half2_rn((qf.x + vf.x) * SCALE_LOG2E, (qf.y + vf.y) * SCALE_LOG2E);
    }

    float mi0 = -INFINITY, mi1 = -INFINITY;
    float o[8][4], osum[4];
    #pragma unroll
    for (int nt = 0; nt < 8; nt++)
        #pragma unroll
        for (int i = 0; i < 4; i++) o[nt][i] = 0.f;
    #pragma unroll
    for (int i = 0; i < 4; i++) osum[i] = 0.f;

    for (int kt = 0; kt < LL / 64; kt++) {
        CP_WAIT0;
        __syncthreads();
        int cur = kt & 1;
        if (kt + 1 < LL / 64) {
            int nb = (kt + 1) & 1;
            __half* dKP = sKP + nb * 64 * ATL;
            __half* dVT = sVT + nb * VTROWS * VTL;
            int kbase = (kt + 1) * 64;
            for (int idx = tid; idx < 512; idx += 256) {
                int m = idx >> 3, c8 = (idx & 7) << 3;
                cpa16(dKP + m * ATL + c8,      kb  + (size_t)(kbase + m) * DH + c8);
                cpa16(dKP + m * ATL + 64 + c8, pb  + (size_t)(kbase + m) * DH + c8);
                cpa16(dVT + m * VTL + c8,      vtb + (size_t)m * LL + kbase + c8);
            }
            CP_COMMIT;
        }
        const __half* KPb = sKP + cur * 64 * ATL;
        const __half* VTb = sVT + cur * VTROWS * VTL;

        // scores (log2 units): warp tile 16(m) x 64(n), K=128
        float s[8][4];
        #pragma unroll
        for (int nt = 0; nt < 8; nt++)
            #pragma unroll
            for (int i = 0; i < 4; i++) s[nt][i] = 0.f;
        #pragma unroll
        for (int kk = 0; kk < 128; kk += 16) {
            unsigned a[4];
            ldsm4(a, sA + (wr + l15) * ATL + kk + lh);
            #pragma unroll
            for (int pr = 0; pr < 4; pr++) {
                unsigned bb[4];
                ldsm4(bb, KPb + (pr*16 + bnp + bn8) * ATL + kk + bkh);
                mma_f16(s[2*pr],     a, &bb[0]);
                mma_f16(s[2*pr + 1], a, &bb[2]);
            }
        }

        // register softmax (log2 units): rows r0 = wr+g, r1 = wr+g+8
        float m0 = -INFINITY, m1 = -INFINITY;
        #pragma unroll
        for (int nt = 0; nt < 8; nt++) {
            m0 = fmaxf(m0, fmaxf(s[nt][0], s[nt][1]));
            m1 = fmaxf(m1, fmaxf(s[nt][2], s[nt][3]));
        }
        m0 = fmaxf(m0, __shfl_xor_sync(0xffffffffu, m0, 1));
        m0 = fmaxf(m0, __shfl_xor_sync(0xffffffffu, m0, 2));
        m1 = fmaxf(m1, __shfl_xor_sync(0xffffffffu, m1, 1));
        m1 = fmaxf(m1, __shfl_xor_sync(0xffffffffu, m1, 2));
        float newm0 = fmaxf(mi0, m0), newm1 = fmaxf(mi1, m1);
        float alpha0 = ex2(mi0 - newm0), alpha1 = ex2(mi1 - newm1);
        mi0 = newm0; mi1 = newm1;
        unsigned pa[4][4];
        #pragma unroll
        for (int nt = 0; nt < 8; nt++) {
            float p0 = ex2(s[nt][0] - newm0);
            float p1 = ex2(s[nt][1] - newm0);
            float p2 = ex2(s[nt][2] - newm1);
            float p3 = ex2(s[nt][3] - newm1);
            unsigned lo = pack_h2(p0, p1);
            unsigned hi = pack_h2(p2, p3);
            pa[nt >> 1][(nt & 1) ? 2 : 0] = lo;
            pa[nt >> 1][(nt & 1) ? 3 : 1] = hi;
        }

        // rescale O + li-accumulator, then AV (+ ones-column row-sum)
        #pragma unroll
        for (int nt = 0; nt < 8; nt++) {
            o[nt][0] *= alpha0; o[nt][1] *= alpha0;
            o[nt][2] *= alpha1; o[nt][3] *= alpha1;
        }
        osum[0] *= alpha0; osum[1] *= alpha0;
        osum[2] *= alpha1; osum[3] *= alpha1;
        #pragma unroll
        for (int kc = 0; kc < 4; kc++) {
            #pragma unroll
            for (int pr = 0; pr < 4; pr++) {
                unsigned bb[4];
                ldsm4(bb, VTb + (pr*16 + bnp + bn8) * VTL + kc*16 + bkh);
                mma_f16(o[2*pr],     pa[kc], &bb[0]);
                mma_f16(o[2*pr + 1], pa[kc], &bb[2]);
            }
            unsigned bs[4];
            ldsm4(bs, VTb + (64 + bnp + bn8) * VTL + kc*16 + bkh);
            mma_f16(osum, pa[kc], &bs[0]);     // col 0 of this tile = ones
        }
    }

    // finalize: li = osum col0 (held by t4==0 lanes) — broadcast across quad
    int src = lane & ~3;
    float li0 = __shfl_sync(0xffffffffu, osum[0], src);
    float li1 = __shfl_sync(0xffffffffu, osum[2], src);
    float inv0 = 1.f / li0, inv1 = 1.f / li1;
    int r0 = wr + g;
    __half* ob1 = g_att + ((size_t)(b * LL + q0 + r0))     * INNER + h * DH;
    __half* ob2 = g_att + ((size_t)(b * LL + q0 + r0 + 8)) * INNER + h * DH;
    #pragma unroll
    for (int nt = 0; nt < 8; nt++) {
        int dh0 = nt*8 + t4*2;
        *(__half2*)(ob1 + dh0) = __floats2half2_rn(o[nt][0] * inv0, o[nt][1] * inv0);
        *(__half2*)(ob2 + dh0) = __floats2half2_rn(o[nt][2] * inv1, o[nt][3] * inv1);
    }
}

// ---------------- launch ----------------
extern "C" void kernel_launch(void* const* d_in, const int* in_sizes, int n_in,
                              void* d_out, int out_size) {
    const float* x      = (const float*)d_in[0];
    const float* gamma  = (const float*)d_in[1];
    const float* beta   = (const float*)d_in[2];
    const float* w_qkv  = (const float*)d_in[3];
    const float* b_qkv  = (const float*)d_in[4];
    const float* w_pos  = (const float*)d_in[5];
    const float* w_out  = (const float*)d_in[6];
    const float* b_out  = (const float*)d_in[7];
    const float* u_bias = (const float*)d_in[8];
    const float* v_bias = (const float*)d_in[9];
    float* out = (float*)d_out;

    // 1. convert weights to half + freq table
    {
        int n4 = (3*INNER*DD + INNER*DD + DD*INNER) / 4;
        cvt_w<<<(n4 + 255) / 256, 256>>>(w_qkv, w_pos, w_out);
    }

    // 2. fused LayerNorm (warp/row) + PE table
    ln_pe_kernel<<<ROWS/8 + (LL*DD)/256, 256>>>(x, gamma, beta);

    // 3. fused QKV GEMM + pos GEMM
    {
        dim3 grid((3 * INNER) / 128, ROWS / 128, 2);
        gemm_fused<<<grid, 256>>>(b_qkv);
    }

    // 4. attention
    {
        int smem = ATT_SMEM_BYTES;   // ~93 KB
        cudaFuncSetAttribute(attn_tc, cudaFuncAttributeMaxDynamicSharedMemorySize, smem);
        dim3 grid(LL / 128, BB * HH);
        attn_tc<<<grid, 256, smem>>>(u_bias, v_bias);
    }

    // 5. out projection -> d_out
    {
        dim3 grid(DD / 128, ROWS / 128);
        gemm_out<<<grid, 256>>>(b_out, out);
    }
}

// round 14
// speedup vs baseline: 2.5408x; 1.0092x over previous
#include <cuda_runtime.h>
#include <cuda_fp16.h>
#include <math.h>

// Problem constants
#define BB 8
#define LL 1024
#define DD 512
#define HH 8
#define DH 64
#define INNER 512
#define ROWS (BB*LL)          // 8192
#define EPSV 1e-5f
#define SCALE_LOG2E 0.18033688011112042f   // 0.125 * log2(e)

// ---------------- scratch (device globals; no allocation) ----------------
__device__ __half  g_xn [ROWS*DD];
__device__ __half  g_pe [LL*DD];
__device__ __half  g_pos[HH*LL*DH];
__device__ __half  g_q  [BB*HH*LL*DH];
__device__ __half  g_k  [BB*HH*LL*DH];
__device__ __half  g_v  [BB*HH*DH*LL];     // TRANSPOSED: [bh][dh][l]
__device__ __half  g_att[ROWS*INNER];
__device__ __half  g_wqkv[3*INNER*DD];
__device__ __half  g_wpos[INNER*DD];
__device__ __half  g_wout[DD*INNER];
__device__ double  g_freq[DD];

// ---------------- helpers ----------------
__device__ __forceinline__ void mma_f16(float c[4], const unsigned a[4], const unsigned b[2]) {
    asm volatile(
        "mma.sync.aligned.m16n8k16.row.col.f32.f16.f16.f32 "
        "{%0,%1,%2,%3}, {%4,%5,%6,%7}, {%8,%9}, {%0,%1,%2,%3};"
        : "+f"(c[0]), "+f"(c[1]), "+f"(c[2]), "+f"(c[3])
        : "r"(a[0]), "r"(a[1]), "r"(a[2]), "r"(a[3]), "r"(b[0]), "r"(b[1]));
}

__device__ __forceinline__ void ldsm4(unsigned r[4], const __half* p) {
    unsigned addr = (unsigned)__cvta_generic_to_shared((void*)p);
    asm volatile("ldmatrix.sync.aligned.m8n8.x4.shared.b16 {%0,%1,%2,%3}, [%4];"
        : "=r"(r[0]), "=r"(r[1]), "=r"(r[2]), "=r"(r[3]) : "r"(addr));
}

__device__ __forceinline__ unsigned pack_h2(float x, float y) {
    unsigned r;
    asm("cvt.rn.f16x2.f32 %0, %1, %2;" : "=r"(r) : "f"(y), "f"(x));
    return r;
}

__device__ __forceinline__ float ex2(float x) {
    float r;
    asm("ex2.approx.ftz.f32 %0, %1;" : "=f"(r) : "f"(x));
    return r;
}

__device__ __forceinline__ void cpa16(void* dst_smem, const void* src) {
    unsigned d = (unsigned)__cvta_generic_to_shared(dst_smem);
    asm volatile("cp.async.cg.shared.global [%0], [%1], 16;" :: "r"(d), "l"(src));
}
#define CP_COMMIT asm volatile("cp.async.commit_group;")
#define CP_WAIT0  asm volatile("cp.async.wait_group 0;")

// ---------------- convert weights to half + freq table (one launch) -------
__global__ void cvt_w(const float* __restrict__ wq, const float* __restrict__ wp,
                      const float* __restrict__ wo) {
    const int n1 = 3*INNER*DD/4, n2 = INNER*DD/4, n3 = DD*INNER/4;
    int i = blockIdx.x * blockDim.x + threadIdx.x;
    if (i < DD) g_freq[i] = exp(-(double)i * (log(10000.0) / 256.0));
    float4 v; __half* dst;
    if (i < n1) {
        v = ((const float4*)wq)[i]; dst = g_wqkv + 4*i;
    } else if (i < n1 + n2) {
        v = ((const float4*)wp)[i - n1]; dst = g_wpos + 4*(i - n1);
    } else if (i < n1 + n2 + n3) {
        v = ((const float4*)wo)[i - n1 - n2]; dst = g_wout + 4*(i - n1 - n2);
    } else return;
    *(__half2*)(dst)     = __floats2half2_rn(v.x, v.y);
    *(__half2*)(dst + 2) = __floats2half2_rn(v.z, v.w);
}

// ---------------- fused LayerNorm (warp per row) + PE table ----------------
__global__ void ln_pe_kernel(const float* __restrict__ x,
                             const float* __restrict__ gamma,
                             const float* __restrict__ beta) {
    int tid = threadIdx.x, lane = tid & 31, warp = tid >> 5;
    if (blockIdx.x < ROWS / 8) {
        int row = blockIdx.x * 8 + warp;
        const float* xr = x + (size_t)row * DD;
        float4 v[4];
        float s = 0.f, sq = 0.f;
        #pragma unroll
        for (int k = 0; k < 4; k++) {
            v[k] = *(const float4*)(xr + k * 128 + lane * 4);
            s  += v[k].x + v[k].y + v[k].z + v[k].w;
            sq += v[k].x*v[k].x + v[k].y*v[k].y + v[k].z*v[k].z + v[k].w*v[k].w;
        }
        #pragma unroll
        for (int o = 16; o; o >>= 1) {
            s  += __shfl_xor_sync(0xffffffffu, s,  o);
            sq += __shfl_xor_sync(0xffffffffu, sq, o);
        }
        float mu  = s * (1.f / DD);
        float var = fmaxf(sq * (1.f / DD) - mu * mu, 0.f);
        float rs  = rsqrtf(var + EPSV);
        __half* o = g_xn + (size_t)row * DD;
        #pragma unroll
        for (int k = 0; k < 4; k++) {
            int c = k * 128 + lane * 4;
            float4 gm = *(const float4*)(gamma + c);
            float4 bt = *(const float4*)(beta + c);
            *(__half2*)(o + c)     = __floats2half2_rn((v[k].x - mu)*rs*gm.x + bt.x,
                                                       (v[k].y - mu)*rs*gm.y + bt.y);
            *(__half2*)(o + c + 2) = __floats2half2_rn((v[k].z - mu)*rs*gm.z + bt.z,
                                                       (v[k].w - mu)*rs*gm.w + bt.w);
        }
    } else {
        int idx = (blockIdx.x - ROWS / 8) * 256 + tid;
        if (idx >= LL * DD) return;
        int i = idx >> 9;
        int j = idx & 511;
        double angle = (double)(i - j) * g_freq[j];
        double n = rint(angle * 0.15915494309189535);   // 1/(2*pi)
        double r = angle - n * 6.283185307179586;       // reduced to [-pi, pi]
        float rf = (float)r;
        g_pe[idx] = __float2half_rn(((j & 1) == 0) ? cosf(rf) : sinf(rf));
    }
}

// ---------------- FP16 TC GEMM body, 128x128 tile, K-stage 64, dbl buffer --
#define HLD 72
#define GSTAGE (128 * HLD)
template<int MODE>
__device__ __forceinline__ void gemm_body(__half* As, __half* Bs,
                        const __half* __restrict__ A, const __half* __restrict__ Bt,
                        const float* __restrict__ bias, float* __restrict__ C,
                        int M, int N, int K, int bxx, int byy) {
    int tid  = threadIdx.x, lane = tid & 31, warp = tid >> 5;
    int wm = warp >> 2, wn = warp & 3;     // 2 x 4, warp tile 64x32
    int g  = lane >> 2, t4 = lane & 3;
    int bm = byy * 128, bn = bxx * 128;
    // LDSM per-lane addressing
    int l15 = lane & 15, lh = (lane >> 4) << 3;                 // A: row, k-half
    int bn8 = lane & 7, bkh = ((lane >> 3) & 1) << 3, bnp = (lane >> 4) << 3; // B

    float c[4][4][4];
    #pragma unroll
    for (int mt = 0; mt < 4; mt++)
        #pragma unroll
        for (int nt = 0; nt < 4; nt++)
            #pragma unroll
            for (int i = 0; i < 4; i++) c[mt][nt][i] = 0.f;

    int nstg = K >> 6;   // K/64
    int ldr = tid >> 1, ldc = (tid & 1) << 5;   // 128 rows x 2 half-chunks(32)
    {
        const __half* a0 = A  + (size_t)(bm + ldr) * K + ldc;
        const __half* b0 = Bt + (size_t)(bn + ldr) * K + ldc;
        __half* da = As + ldr * HLD + ldc;
        __half* db = Bs + ldr * HLD + ldc;
        cpa16(da, a0); cpa16(da + 8, a0 + 8); cpa16(da + 16, a0 + 16); cpa16(da + 24, a0 + 24);
        cpa16(db, b0); cpa16(db + 8, b0 + 8); cpa16(db + 16, b0 + 16); cpa16(db + 24, b0 + 24);
        CP_COMMIT;
    }
    for (int s = 0; s < nstg; s++) {
        CP_WAIT0; __syncthreads();
        if (s + 1 < nstg) {
            int buf = (s + 1) & 1, k0 = (s + 1) << 6;
            const __half* a0 = A  + (size_t)(bm + ldr) * K + k0 + ldc;
            const __half* b0 = Bt + (size_t)(bn + ldr) * K + k0 + ldc;
            __half* da = As + buf * GSTAGE + ldr * HLD + ldc;
            __half* db = Bs + buf * GSTAGE + ldr * HLD + ldc;
            cpa16(da, a0); cpa16(da + 8, a0 + 8); cpa16(da + 16, a0 + 16); cpa16(da + 24, a0 + 24);
            cpa16(db, b0); cpa16(db + 8, b0 + 8); cpa16(db + 16, b0 + 16); cpa16(db + 24, b0 + 24);
            CP_COMMIT;
        }
        const __half* Ab = As + (s & 1) * GSTAGE;
        const __half* Bb = Bs + (s & 1) * GSTAGE;
        #pragma unroll
        for (int kk = 0; kk < 64; kk += 16) {
            unsigned a[4][4], b01[4], b23[4];
            #pragma unroll
            for (int mt = 0; mt < 4; mt++)
                ldsm4(a[mt], Ab + (wm*64 + mt*16 + l15) * HLD + kk + lh);
            ldsm4(b01, Bb + (wn*32 +      bnp + bn8) * HLD + kk + bkh);
            ldsm4(b23, Bb + (wn*32 + 16 + bnp + bn8) * HLD + kk + bkh);
            #pragma unroll
            for (int mt = 0; mt < 4; mt++) {
                mma_f16(c[mt][0], a[mt], &b01[0]);
                mma_f16(c[mt][1], a[mt], &b01[2]);
                mma_f16(c[mt][2], a[mt], &b23[0]);
                mma_f16(c[mt][3], a[mt], &b23[2]);
            }
        }
        // no trailing barrier: next iteration's leading sync (after CP_WAIT0)
        // already orders all compute(s) before any prefetch into this buffer.
    }

    // epilogue (paired stores where destinations are contiguous)
    #pragma unroll
    for (int mt = 0; mt < 4; mt++) {
        #pragma unroll
        for (int nt = 0; nt < 4; nt++) {
            int r0 = bm + wm*64 + mt*16 + g;
            int c0 = bn + wn*32 + nt*8 + t4*2;
            #pragma unroll
            for (int half_ = 0; half_ < 2; half_++) {
                int r = r0 + (half_ ? 8 : 0);
                float v0 = c[mt][nt][2*half_ + 0] + (bias ? bias[c0]     : 0.f);
                float v1 = c[mt][nt][2*half_ + 1] + (bias ? bias[c0 + 1] : 0.f);
                if (MODE == 0) {
                    *(float2*)(C + (size_t)r * N + c0) = make_float2(v0, v1);
                } else if (MODE == 1) {
                    int which = c0 >> 9, rem = c0 & 511;
                    int h = rem >> 6, dh = rem & 63;
                    int b_ = r >> 10, l = r & 1023;
                    if (which == 0)
                        *(__half2*)(g_q + (((size_t)b_ * HH + h) * LL + l) * DH + dh)
                            = __floats2half2_rn(v0, v1);
                    else if (which == 1)
                        *(__half2*)(g_k + (((size_t)b_ * HH + h) * LL + l) * DH + dh)
                            = __floats2half2_rn(v0, v1);
                    else {  // V transposed: [bh][dh][l] — dh not contiguous
                        g_v[(((size_t)b_ * HH + h) * DH + dh)     * LL + l] = __float2half_rn(v0);
                        g_v[(((size_t)b_ * HH + h) * DH + dh + 1) * LL + l] = __float2half_rn(v1);
                    }
                } else {
                    int h = c0 >> 6, dh = c0 & 63;
                    *(__half2*)(g_pos + ((size_t)h * LL + r) * DH + dh)
                        = __floats2half2_rn(v0, v1);
                }
            }
        }
    }
}

__global__ __launch_bounds__(256, 2) void gemm_fused(const float* __restrict__ b_qkv) {
    __shared__ __half As[2 * GSTAGE];
    __shared__ __half Bs[2 * GSTAGE];
    if (blockIdx.z == 0) {
        gemm_body<1>(As, Bs, g_xn, g_wqkv, b_qkv, nullptr, ROWS, 3*INNER, DD,
                     blockIdx.x, blockIdx.y);
    } else {
        if (blockIdx.x >= INNER/128 || blockIdx.y >= LL/128) return;
        gemm_body<2>(As, Bs, g_pe, g_wpos, nullptr, nullptr, LL, INNER, DD,
                     blockIdx.x, blockIdx.y);
    }
}

__global__ __launch_bounds__(256, 2) void gemm_out(const float* __restrict__ b_out,
                                                   float* __restrict__ out) {
    __shared__ __half As[2 * GSTAGE];
    __shared__ __half Bs[2 * GSTAGE];
    gemm_body<0>(As, Bs, g_att, g_wout, b_out, out, ROWS, DD, INNER,
                 blockIdx.x, blockIdx.y);
}

// ---------------- flash attention: log2 softmax + constant ones-fragment ---
// Q pre-scaled by 0.125*log2e so scores are in log2 units: p = ex2(s - m).
// li accumulated via mma against a CONSTANT ones B-fragment (no smem rows).
#define ATL  136   // sA / sKP row stride (halves)
#define VTL  72    // sVT row stride (halves)
#define N_SA  (128 * ATL)
#define N_SKP (2 * 64 * ATL)
#define N_SVT (2 * 64 * VTL)
#define ATT_SMEM_BYTES ((N_SA + N_SKP + N_SVT) * 2)   // ~86 KB

__global__ __launch_bounds__(256, 2) void attn_tc(const float* __restrict__ u_bias,
                                                  const float* __restrict__ v_bias) {
    extern __shared__ char smbase[];
    __half* sA  = (__half*)smbase;
    __half* sKP = sA  + N_SA;
    __half* sVT = sKP + N_SKP;

    int tid = threadIdx.x, lane = tid & 31, warp = tid >> 5;
    int g  = lane >> 2, t4 = lane & 3;
    int wr = warp * 16;
    int bh = blockIdx.y, b = bh >> 3, h = bh & 7;
    int q0 = blockIdx.x * 128;
    int l15 = lane & 15, lh = (lane >> 4) << 3;
    int bn8 = lane & 7, bkh = ((lane >> 3) & 1) << 3, bnp = (lane >> 4) << 3;

    // constant ones B-fragment: n = lane>>2 within n-tile; row 0 = ones
    unsigned onesf[2];
    onesf[0] = onesf[1] = (g == 0) ? 0x3C003C00u : 0u;

    const __half* qb  = g_q   + (size_t)bh * LL * DH;
    const __half* kb  = g_k   + (size_t)bh * LL * DH;
    const __half* vtb = g_v   + (size_t)bh * DH * LL;
    const __half* pb  = g_pos + (size_t)h  * LL * DH;

    for (int idx = tid; idx < 512; idx += 256) {
        int m = idx >> 3, c8 = (idx & 7) << 3;
        cpa16(sKP + m * ATL + c8,      kb  + (size_t)m * DH + c8);
        cpa16(sKP + m * ATL + 64 + c8, pb  + (size_t)m * DH + c8);
        cpa16(sVT + m * VTL + c8,      vtb + (size_t)m * LL + c8);
    }
    CP_COMMIT;

    // build sA = (Q+u | Q+v) * 0.125*log2e  (half)
    for (int idx = tid; idx < 4096; idx += 256) {
        int r = idx >> 5, c2 = idx & 31;
        float2 qf = __half22float2(*(const __half2*)(qb + (size_t)(q0 + r) * DH + 2*c2));
        float2 uf = *(const float2*)(u_bias + h * DH + 2*c2);
        float2 vf = *(const float2*)(v_bias + h * DH + 2*c2);
        *(__half2*)(sA + r * ATL + 2*c2)
            = __floats2half2_rn((qf.x + uf.x) * SCALE_LOG2E, (qf.y + uf.y) * SCALE_LOG2E);
        *(__half2*)(sA + r * ATL + 64 + 2*c2)
            = __floats2half2_rn((qf.x + vf.x) * SCALE_LOG2E, (qf.y + vf.y) * SCALE_LOG2E);
    }

    float mi0 = -INFINITY, mi1 = -INFINITY;
    float o[8][4], osum[4];
    #pragma unroll
    for (int nt = 0; nt < 8; nt++)
        #pragma unroll
        for (int i = 0; i < 4; i++) o[nt][i] = 0.f;
    #pragma unroll
    for (int i = 0; i < 4; i++) osum[i] = 0.f;

    for (int kt = 0; kt < LL / 64; kt++) {
        CP_WAIT0;
        __syncthreads();
        int cur = kt & 1;
        if (kt + 1 < LL / 64) {
            int nb = (kt + 1) & 1;
            __half* dKP = sKP + nb * 64 * ATL;
            __half* dVT = sVT + nb * 64 * VTL;
            int kbase = (kt + 1) * 64;
            for (int idx = tid; idx < 512; idx += 256) {
                int m = idx >> 3, c8 = (idx & 7) << 3;
                cpa16(dKP + m * ATL + c8,      kb  + (size_t)(kbase + m) * DH + c8);
                cpa16(dKP + m * ATL + 64 + c8, pb  + (size_t)(kbase + m) * DH + c8);
                cpa16(dVT + m * VTL + c8,      vtb + (size_t)m * LL + kbase + c8);
            }
            CP_COMMIT;
        }
        const __half* KPb = sKP + cur * 64 * ATL;
        const __half* VTb = sVT + cur * 64 * VTL;

        // scores (log2 units): warp tile 16(m) x 64(n), K=128
        float s[8][4];
        #pragma unroll
        for (int nt = 0; nt < 8; nt++)
            #pragma unroll
            for (int i = 0; i < 4; i++) s[nt][i] = 0.f;
        #pragma unroll
        for (int kk = 0; kk < 128; kk += 16) {
            unsigned a[4];
            ldsm4(a, sA + (wr + l15) * ATL + kk + lh);
            #pragma unroll
            for (int pr = 0; pr < 4; pr++) {
                unsigned bb[4];
                ldsm4(bb, KPb + (pr*16 + bnp + bn8) * ATL + kk + bkh);
                mma_f16(s[2*pr],     a, &bb[0]);
                mma_f16(s[2*pr + 1], a, &bb[2]);
            }
        }

        // register softmax (log2 units)
        float m0 = -INFINITY, m1 = -INFINITY;
        #pragma unroll
        for (int nt = 0; nt < 8; nt++) {
            m0 = fmaxf(m0, fmaxf(s[nt][0], s[nt][1]));
            m1 = fmaxf(m1, fmaxf(s[nt][2], s[nt][3]));
        }
        m0 = fmaxf(m0, __shfl_xor_sync(0xffffffffu, m0, 1));
        m0 = fmaxf(m0, __shfl_xor_sync(0xffffffffu, m0, 2));
        m1 = fmaxf(m1, __shfl_xor_sync(0xffffffffu, m1, 1));
        m1 = fmaxf(m1, __shfl_xor_sync(0xffffffffu, m1, 2));
        float newm0 = fmaxf(mi0, m0), newm1 = fmaxf(mi1, m1);
        float alpha0 = ex2(mi0 - newm0), alpha1 = ex2(mi1 - newm1);
        mi0 = newm0; mi1 = newm1;
        unsigned pa[4][4];
        #pragma unroll
        for (int nt = 0; nt < 8; nt++) {
            float p0 = ex2(s[nt][0] - newm0);
            float p1 = ex2(s[nt][1] - newm0);
            float p2 = ex2(s[nt][2] - newm1);
            float p3 = ex2(s[nt][3] - newm1);
            unsigned lo = pack_h2(p0, p1);
            unsigned hi = pack_h2(p2, p3);
            pa[nt >> 1][(nt & 1) ? 2 : 0] = lo;
            pa[nt >> 1][(nt & 1) ? 3 : 1] = hi;
        }

        // rescale O + li-accumulator, then AV (+ constant ones-frag row-sum)
        #pragma unroll
        for (int nt = 0; nt < 8; nt++) {
            o[nt][0] *= alpha0; o[nt][1] *= alpha0;
            o[nt][2] *= alpha1; o[nt][3] *= alpha1;
        }
        osum[0] *= alpha0; osum[1] *= alpha0;
        osum[2] *= alpha1; osum[3] *= alpha1;
        #pragma unroll
        for (int kc = 0; kc < 4; kc++) {
            #pragma unroll
            for (int pr = 0; pr < 4; pr++) {
                unsigned bb[4];
                ldsm4(bb, VTb + (pr*16 + bnp + bn8) * VTL + kc*16 + bkh);
                mma_f16(o[2*pr],     pa[kc], &bb[0]);
                mma_f16(o[2*pr + 1], pa[kc], &bb[2]);
            }
            mma_f16(osum, pa[kc], onesf);   // col 0 accumulates row-sum
        }
    }

    // finalize: li = osum col0 (held by t4==0 lanes) — broadcast across quad
    int src = lane & ~3;
    float li0 = __shfl_sync(0xffffffffu, osum[0], src);
    float li1 = __shfl_sync(0xffffffffu, osum[2], src);
    float inv0 = 1.f / li0, inv1 = 1.f / li1;
    int r0 = wr + g;
    __half* ob1 = g_att + ((size_t)(b * LL + q0 + r0))     * INNER + h * DH;
    __half* ob2 = g_att + ((size_t)(b * LL + q0 + r0 + 8)) * INNER + h * DH;
    #pragma unroll
    for (int nt = 0; nt < 8; nt++) {
        int dh0 = nt*8 + t4*2;
        *(__half2*)(ob1 + dh0) = __floats2half2_rn(o[nt][0] * inv0, o[nt][1] * inv0);
        *(__half2*)(ob2 + dh0) = __floats2half2_rn(o[nt][2] * inv1, o[nt][3] * inv1);
    }
}

// ---------------- launch ----------------
extern "C" void kernel_launch(void* const* d_in, const int* in_sizes, int n_in,
                              void* d_out, int out_size) {
    const float* x      = (const float*)d_in[0];
    const float* gamma  = (const float*)d_in[1];
    const float* beta   = (const float*)d_in[2];
    const float* w_qkv  = (const float*)d_in[3];
    const float* b_qkv  = (const float*)d_in[4];
    const float* w_pos  = (const float*)d_in[5];
    const float* w_out  = (const float*)d_in[6];
    const float* b_out  = (const float*)d_in[7];
    const float* u_bias = (const float*)d_in[8];
    const float* v_bias = (const float*)d_in[9];
    float* out = (float*)d_out;

    // 1. convert weights to half + freq table
    {
        int n4 = (3*INNER*DD + INNER*DD + DD*INNER) / 4;
        cvt_w<<<(n4 + 255) / 256, 256>>>(w_qkv, w_pos, w_out);
    }

    // 2. fused LayerNorm (warp/row) + PE table
    ln_pe_kernel<<<ROWS/8 + (LL*DD)/256, 256>>>(x, gamma, beta);

    // 3. fused QKV GEMM + pos GEMM
    {
        dim3 grid((3 * INNER) / 128, ROWS / 128, 2);
        gemm_fused<<<grid, 256>>>(b_qkv);
    }

    // 4. attention
    {
        int smem = ATT_SMEM_BYTES;   // ~86 KB
        cudaFuncSetAttribute(attn_tc, cudaFuncAttributeMaxDynamicSharedMemorySize, smem);
        dim3 grid(LL / 128, BB * HH);
        attn_tc<<<grid, 256, smem>>>(u_bias, v_bias);
    }

    // 5. out projection -> d_out
    {
        dim3 grid(DD / 128, ROWS / 128);
        gemm_out<<<grid, 256>>>(b_out, out);
    }
}

// round 15
// speedup vs baseline: 2.5420x; 1.0005x over previous
#include <cuda_runtime.h>
#include <cuda_fp16.h>
#include <math.h>

// Problem constants
#define BB 8
#define LL 1024
#define DD 512
#define HH 8
#define DH 64
#define INNER 512
#define ROWS (BB*LL)          // 8192
#define EPSV 1e-5f
#define SCALE_LOG2E 0.18033688011112042f   // 0.125 * log2(e)

// ---------------- scratch (device globals; no allocation) ----------------
__device__ __half  g_xn [ROWS*DD];
__device__ __half  g_pe [LL*DD];
__device__ __half  g_pos[HH*LL*DH];
__device__ __half  g_q  [BB*HH*LL*DH];
__device__ __half  g_k  [BB*HH*LL*DH];
__device__ __half  g_v  [BB*HH*DH*LL];     // TRANSPOSED: [bh][dh][l]
__device__ __half  g_att[ROWS*INNER];
__device__ __half  g_wqkv[3*INNER*DD];
__device__ __half  g_wpos[INNER*DD];
__device__ __half  g_wout[DD*INNER];
__device__ double  g_freq[DD];

// ---------------- helpers ----------------
__device__ __forceinline__ void mma_f16(float c[4], const unsigned a[4], const unsigned b[2]) {
    asm volatile(
        "mma.sync.aligned.m16n8k16.row.col.f32.f16.f16.f32 "
        "{%0,%1,%2,%3}, {%4,%5,%6,%7}, {%8,%9}, {%0,%1,%2,%3};"
        : "+f"(c[0]), "+f"(c[1]), "+f"(c[2]), "+f"(c[3])
        : "r"(a[0]), "r"(a[1]), "r"(a[2]), "r"(a[3]), "r"(b[0]), "r"(b[1]));
}

__device__ __forceinline__ void ldsm4(unsigned r[4], const __half* p) {
    unsigned addr = (unsigned)__cvta_generic_to_shared((void*)p);
    asm volatile("ldmatrix.sync.aligned.m8n8.x4.shared.b16 {%0,%1,%2,%3}, [%4];"
        : "=r"(r[0]), "=r"(r[1]), "=r"(r[2]), "=r"(r[3]) : "r"(addr));
}

__device__ __forceinline__ unsigned pack_h2(float x, float y) {
    unsigned r;
    asm("cvt.rn.f16x2.f32 %0, %1, %2;" : "=r"(r) : "f"(y), "f"(x));
    return r;
}

__device__ __forceinline__ float ex2(float x) {
    float r;
    asm("ex2.approx.ftz.f32 %0, %1;" : "=f"(r) : "f"(x));
    return r;
}

__device__ __forceinline__ void cpa16(void* dst_smem, const void* src) {
    unsigned d = (unsigned)__cvta_generic_to_shared(dst_smem);
    asm volatile("cp.async.cg.shared.global [%0], [%1], 16;" :: "r"(d), "l"(src));
}
#define CP_COMMIT asm volatile("cp.async.commit_group;")
#define CP_WAIT0  asm volatile("cp.async.wait_group 0;")

// ---------------- freq table (tiny, must precede fused kernel) ------------
__global__ void freq_kernel() {
    int j = threadIdx.x + blockIdx.x * blockDim.x;
    if (j < DD) g_freq[j] = exp(-(double)j * (log(10000.0) / 256.0));
}

// ---------------- fused LayerNorm + PE table + weight conversion ----------
#define LN_BLKS   (ROWS / 8)              // 1024
#define PE_BLKS   ((LL * DD) / 256)       // 2048
#define CVT_N4    ((3*INNER*DD + INNER*DD + DD*INNER) / 4)   // 327680
#define CVT_BLKS  ((CVT_N4 + 255) / 256)  // 1280
__global__ void ln_pe_cvt_kernel(const float* __restrict__ x,
                                 const float* __restrict__ gamma,
                                 const float* __restrict__ beta,
                                 const float* __restrict__ wq,
                                 const float* __restrict__ wp,
                                 const float* __restrict__ wo) {
    int tid = threadIdx.x, lane = tid & 31, warp = tid >> 5;
    if (blockIdx.x < LN_BLKS) {
        int row = blockIdx.x * 8 + warp;
        const float* xr = x + (size_t)row * DD;
        float4 v[4];
        float s = 0.f, sq = 0.f;
        #pragma unroll
        for (int k = 0; k < 4; k++) {
            v[k] = *(const float4*)(xr + k * 128 + lane * 4);
            s  += v[k].x + v[k].y + v[k].z + v[k].w;
            sq += v[k].x*v[k].x + v[k].y*v[k].y + v[k].z*v[k].z + v[k].w*v[k].w;
        }
        #pragma unroll
        for (int o = 16; o; o >>= 1) {
            s  += __shfl_xor_sync(0xffffffffu, s,  o);
            sq += __shfl_xor_sync(0xffffffffu, sq, o);
        }
        float mu  = s * (1.f / DD);
        float var = fmaxf(sq * (1.f / DD) - mu * mu, 0.f);
        float rs  = rsqrtf(var + EPSV);
        __half* o = g_xn + (size_t)row * DD;
        #pragma unroll
        for (int k = 0; k < 4; k++) {
            int c = k * 128 + lane * 4;
            float4 gm = *(const float4*)(gamma + c);
            float4 bt = *(const float4*)(beta + c);
            *(__half2*)(o + c)     = __floats2half2_rn((v[k].x - mu)*rs*gm.x + bt.x,
                                                       (v[k].y - mu)*rs*gm.y + bt.y);
            *(__half2*)(o + c + 2) = __floats2half2_rn((v[k].z - mu)*rs*gm.z + bt.z,
                                                       (v[k].w - mu)*rs*gm.w + bt.w);
        }
    } else if (blockIdx.x < LN_BLKS + PE_BLKS) {
        int idx = (blockIdx.x - LN_BLKS) * 256 + tid;
        int i = idx >> 9;
        int j = idx & 511;
        double angle = (double)(i - j) * g_freq[j];
        double n = rint(angle * 0.15915494309189535);   // 1/(2*pi)
        double r = angle - n * 6.283185307179586;       // reduced to [-pi, pi]
        float rf = (float)r;
        g_pe[idx] = __float2half_rn(((j & 1) == 0) ? cosf(rf) : sinf(rf));
    } else {
        const int n1 = 3*INNER*DD/4, n2 = INNER*DD/4, n3 = DD*INNER/4;
        int i = (blockIdx.x - LN_BLKS - PE_BLKS) * 256 + tid;
        float4 v; __half* dst;
        if (i < n1) {
            v = ((const float4*)wq)[i]; dst = g_wqkv + 4*i;
        } else if (i < n1 + n2) {
            v = ((const float4*)wp)[i - n1]; dst = g_wpos + 4*(i - n1);
        } else if (i < n1 + n2 + n3) {
            v = ((const float4*)wo)[i - n1 - n2]; dst = g_wout + 4*(i - n1 - n2);
        } else return;
        *(__half2*)(dst)     = __floats2half2_rn(v.x, v.y);
        *(__half2*)(dst + 2) = __floats2half2_rn(v.z, v.w);
    }
}

// ---------------- FP16 TC GEMM body, 128x128 tile, K-stage 64, dbl buffer --
#define HLD 72
#define GSTAGE (128 * HLD)
template<int MODE>
__device__ __forceinline__ void gemm_body(__half* As, __half* Bs,
                        const __half* __restrict__ A, const __half* __restrict__ Bt,
                        const float* __restrict__ bias, float* __restrict__ C,
                        int M, int N, int K, int bxx, int byy) {
    int tid  = threadIdx.x, lane = tid & 31, warp = tid >> 5;
    int wm = warp >> 2, wn = warp & 3;     // 2 x 4, warp tile 64x32
    int g  = lane >> 2, t4 = lane & 3;
    int bm = byy * 128, bn = bxx * 128;
    // LDSM per-lane addressing
    int l15 = lane & 15, lh = (lane >> 4) << 3;                 // A: row, k-half
    int bn8 = lane & 7, bkh = ((lane >> 3) & 1) << 3, bnp = (lane >> 4) << 3; // B

    float c[4][4][4];
    #pragma unroll
    for (int mt = 0; mt < 4; mt++)
        #pragma unroll
        for (int nt = 0; nt < 4; nt++)
            #pragma unroll
            for (int i = 0; i < 4; i++) c[mt][nt][i] = 0.f;

    int nstg = K >> 6;   // K/64
    int ldr = tid >> 1, ldc = (tid & 1) << 5;   // 128 rows x 2 half-chunks(32)
    // hoisted prefetch pointers (advance by 64 per stage)
    const __half* pa = A  + (size_t)(bm + ldr) * K + ldc;
    const __half* pb = Bt + (size_t)(bn + ldr) * K + ldc;
    __half* da0 = As + ldr * HLD + ldc;
    __half* db0 = Bs + ldr * HLD + ldc;
    {
        cpa16(da0, pa); cpa16(da0 + 8, pa + 8); cpa16(da0 + 16, pa + 16); cpa16(da0 + 24, pa + 24);
        cpa16(db0, pb); cpa16(db0 + 8, pb + 8); cpa16(db0 + 16, pb + 16); cpa16(db0 + 24, pb + 24);
        CP_COMMIT;
        pa += 64; pb += 64;
    }
    for (int s = 0; s < nstg; s++) {
        CP_WAIT0; __syncthreads();
        if (s + 1 < nstg) {
            int buf = (s + 1) & 1;
            __half* da = da0 + buf * GSTAGE;
            __half* db = db0 + buf * GSTAGE;
            cpa16(da, pa); cpa16(da + 8, pa + 8); cpa16(da + 16, pa + 16); cpa16(da + 24, pa + 24);
            cpa16(db, pb); cpa16(db + 8, pb + 8); cpa16(db + 16, pb + 16); cpa16(db + 24, pb + 24);
            CP_COMMIT;
            pa += 64; pb += 64;
        }
        const __half* Ab = As + (s & 1) * GSTAGE;
        const __half* Bb = Bs + (s & 1) * GSTAGE;
        #pragma unroll
        for (int kk = 0; kk < 64; kk += 16) {
            unsigned a[4][4], b01[4], b23[4];
            #pragma unroll
            for (int mt = 0; mt < 4; mt++)
                ldsm4(a[mt], Ab + (wm*64 + mt*16 + l15) * HLD + kk + lh);
            ldsm4(b01, Bb + (wn*32 +      bnp + bn8) * HLD + kk + bkh);
            ldsm4(b23, Bb + (wn*32 + 16 + bnp + bn8) * HLD + kk + bkh);
            #pragma unroll
            for (int mt = 0; mt < 4; mt++) {
                mma_f16(c[mt][0], a[mt], &b01[0]);
                mma_f16(c[mt][1], a[mt], &b01[2]);
                mma_f16(c[mt][2], a[mt], &b23[0]);
                mma_f16(c[mt][3], a[mt], &b23[2]);
            }
        }
        // no trailing barrier: next iteration's leading sync orders reuse
    }

    // epilogue (paired stores where destinations are contiguous)
    #pragma unroll
    for (int mt = 0; mt < 4; mt++) {
        #pragma unroll
        for (int nt = 0; nt < 4; nt++) {
            int r0 = bm + wm*64 + mt*16 + g;
            int c0 = bn + wn*32 + nt*8 + t4*2;
            #pragma unroll
            for (int half_ = 0; half_ < 2; half_++) {
                int r = r0 + (half_ ? 8 : 0);
                float v0 = c[mt][nt][2*half_ + 0] + (bias ? bias[c0]     : 0.f);
                float v1 = c[mt][nt][2*half_ + 1] + (bias ? bias[c0 + 1] : 0.f);
                if (MODE == 0) {
                    *(float2*)(C + (size_t)r * N + c0) = make_float2(v0, v1);
                } else if (MODE == 1) {
                    int which = c0 >> 9, rem = c0 & 511;
                    int h = rem >> 6, dh = rem & 63;
                    int b_ = r >> 10, l = r & 1023;
                    if (which == 0)
                        *(__half2*)(g_q + (((size_t)b_ * HH + h) * LL + l) * DH + dh)
                            = __floats2half2_rn(v0, v1);
                    else if (which == 1)
                        *(__half2*)(g_k + (((size_t)b_ * HH + h) * LL + l) * DH + dh)
                            = __floats2half2_rn(v0, v1);
                    else {  // V transposed: [bh][dh][l] — dh not contiguous
                        g_v[(((size_t)b_ * HH + h) * DH + dh)     * LL + l] = __float2half_rn(v0);
                        g_v[(((size_t)b_ * HH + h) * DH + dh + 1) * LL + l] = __float2half_rn(v1);
                    }
                } else {
                    int h = c0 >> 6, dh = c0 & 63;
                    *(__half2*)(g_pos + ((size_t)h * LL + r) * DH + dh)
                        = __floats2half2_rn(v0, v1);
                }
            }
        }
    }
}

__global__ __launch_bounds__(256, 2) void gemm_fused(const float* __restrict__ b_qkv) {
    __shared__ __half As[2 * GSTAGE];
    __shared__ __half Bs[2 * GSTAGE];
    if (blockIdx.z == 0) {
        gemm_body<1>(As, Bs, g_xn, g_wqkv, b_qkv, nullptr, ROWS, 3*INNER, DD,
                     blockIdx.x, blockIdx.y);
    } else {
        if (blockIdx.x >= INNER/128 || blockIdx.y >= LL/128) return;
        gemm_body<2>(As, Bs, g_pe, g_wpos, nullptr, nullptr, LL, INNER, DD,
                     blockIdx.x, blockIdx.y);
    }
}

__global__ __launch_bounds__(256, 2) void gemm_out(const float* __restrict__ b_out,
                                                   float* __restrict__ out) {
    __shared__ __half As[2 * GSTAGE];
    __shared__ __half Bs[2 * GSTAGE];
    gemm_body<0>(As, Bs, g_att, g_wout, b_out, out, ROWS, DD, INNER,
                 blockIdx.x, blockIdx.y);
}

// ---------------- flash attention: log2 softmax + constant ones-fragment ---
// Q pre-scaled by 0.125*log2e so scores are in log2 units: p = ex2(s - m).
// li accumulated via mma against a CONSTANT ones B-fragment.
// Prefetch pointers hoisted out of the kt loop (advance by constants).
#define ATL  136   // sA / sKP row stride (halves)
#define VTL  72    // sVT row stride (halves)
#define N_SA  (128 * ATL)
#define N_SKP (2 * 64 * ATL)
#define N_SVT (2 * 64 * VTL)
#define ATT_SMEM_BYTES ((N_SA + N_SKP + N_SVT) * 2)   // ~86 KB

__global__ __launch_bounds__(256, 2) void attn_tc(const float* __restrict__ u_bias,
                                                  const float* __restrict__ v_bias) {
    extern __shared__ char smbase[];
    __half* sA  = (__half*)smbase;
    __half* sKP = sA  + N_SA;
    __half* sVT = sKP + N_SKP;

    int tid = threadIdx.x, lane = tid & 31, warp = tid >> 5;
    int g  = lane >> 2, t4 = lane & 3;
    int wr = warp * 16;
    int bh = blockIdx.y, b = bh >> 3, h = bh & 7;
    int q0 = blockIdx.x * 128;
    int l15 = lane & 15, lh = (lane >> 4) << 3;
    int bn8 = lane & 7, bkh = ((lane >> 3) & 1) << 3, bnp = (lane >> 4) << 3;

    // constant ones B-fragment: row 0 of the virtual ones-matrix
    unsigned onesf[2];
    onesf[0] = onesf[1] = (g == 0) ? 0x3C003C00u : 0u;

    const __half* qb  = g_q   + (size_t)bh * LL * DH;
    const __half* kb  = g_k   + (size_t)bh * LL * DH;
    const __half* vtb = g_v   + (size_t)bh * DH * LL;
    const __half* pb  = g_pos + (size_t)h  * LL * DH;

    // hoisted prefetch pointers: thread covers rows m0 and m0+32, column c8
    int m0 = tid >> 3, c8 = (tid & 7) << 3;
    const __half* pk = kb  + (size_t)m0 * DH + c8;
    const __half* pp = pb  + (size_t)m0 * DH + c8;
    const __half* pv = vtb + (size_t)m0 * LL + c8;
    __half* dK0 = sKP + m0 * ATL + c8;
    __half* dV0 = sVT + m0 * VTL + c8;

    // prologue: stage 0
    cpa16(dK0,                pk);
    cpa16(dK0 + 32*ATL,       pk + 32*DH);
    cpa16(dK0 + 64,           pp);
    cpa16(dK0 + 32*ATL + 64,  pp + 32*DH);
    cpa16(dV0,                pv);
    cpa16(dV0 + 32*VTL,       pv + 32*LL);
    CP_COMMIT;
    pk += 64*DH; pp += 64*DH; pv += 64;

    // build sA = (Q+u | Q+v) * 0.125*log2e  (half)
    for (int idx = tid; idx < 4096; idx += 256) {
        int r = idx >> 5, c2 = idx & 31;
        float2 qf = __half22float2(*(const __half2*)(qb + (size_t)(q0 + r) * DH + 2*c2));
        float2 uf = *(const float2*)(u_bias + h * DH + 2*c2);
        float2 vf = *(const float2*)(v_bias + h * DH + 2*c2);
        *(__half2*)(sA + r * ATL + 2*c2)
            = __floats2half2_rn((qf.x + uf.x) * SCALE_LOG2E, (qf.y + uf.y) * SCALE_LOG2E);
        *(__half2*)(sA + r * ATL + 64 + 2*c2)
            = __floats2half2_rn((qf.x + vf.x) * SCALE_LOG2E, (qf.y + vf.y) * SCALE_LOG2E);
    }

    float mi0 = -INFINITY, mi1 = -INFINITY;
    float o[8][4], osum[4];
    #pragma unroll
    for (int nt = 0; nt < 8; nt++)
        #pragma unroll
        for (int i = 0; i < 4; i++) o[nt][i] = 0.f;
    #pragma unroll
    for (int i = 0; i < 4; i++) osum[i] = 0.f;

    for (int kt = 0; kt < LL / 64; kt++) {
        CP_WAIT0;
        __syncthreads();
        int cur = kt & 1;
        if (kt + 1 < LL / 64) {
            int nb = (kt + 1) & 1;
            __half* dK = dK0 + nb * 64 * ATL;
            __half* dV = dV0 + nb * 64 * VTL;
            cpa16(dK,               pk);
            cpa16(dK + 32*ATL,      pk + 32*DH);
            cpa16(dK + 64,          pp);
            cpa16(dK + 32*ATL + 64, pp + 32*DH);
            cpa16(dV,               pv);
            cpa16(dV + 32*VTL,      pv + 32*LL);
            CP_COMMIT;
            pk += 64*DH; pp += 64*DH; pv += 64;
        }
        const __half* KPb = sKP + cur * 64 * ATL;
        const __half* VTb = sVT + cur * 64 * VTL;

        // scores (log2 units): warp tile 16(m) x 64(n), K=128
        float s[8][4];
        #pragma unroll
        for (int nt = 0; nt < 8; nt++)
            #pragma unroll
            for (int i = 0; i < 4; i++) s[nt][i] = 0.f;
        #pragma unroll
        for (int kk = 0; kk < 128; kk += 16) {
            unsigned a[4];
            ldsm4(a, sA + (wr + l15) * ATL + kk + lh);
            #pragma unroll
            for (int pr = 0; pr < 4; pr++) {
                unsigned bb[4];
                ldsm4(bb, KPb + (pr*16 + bnp + bn8) * ATL + kk + bkh);
                mma_f16(s[2*pr],     a, &bb[0]);
                mma_f16(s[2*pr + 1], a, &bb[2]);
            }
        }

        // register softmax (log2 units)
        float m0f = -INFINITY, m1f = -INFINITY;
        #pragma unroll
        for (int nt = 0; nt < 8; nt++) {
            m0f = fmaxf(m0f, fmaxf(s[nt][0], s[nt][1]));
            m1f = fmaxf(m1f, fmaxf(s[nt][2], s[nt][3]));
        }
        m0f = fmaxf(m0f, __shfl_xor_sync(0xffffffffu, m0f, 1));
        m0f = fmaxf(m0f, __shfl_xor_sync(0xffffffffu, m0f, 2));
        m1f = fmaxf(m1f, __shfl_xor_sync(0xffffffffu, m1f, 1));
        m1f = fmaxf(m1f, __shfl_xor_sync(0xffffffffu, m1f, 2));
        float newm0 = fmaxf(mi0, m0f), newm1 = fmaxf(mi1, m1f);
        float alpha0 = ex2(mi0 - newm0), alpha1 = ex2(mi1 - newm1);
        mi0 = newm0; mi1 = newm1;
        unsigned pa4[4][4];
        #pragma unroll
        for (int nt = 0; nt < 8; nt++) {
            float p0 = ex2(s[nt][0] - newm0);
            float p1 = ex2(s[nt][1] - newm0);
            float p2 = ex2(s[nt][2] - newm1);
            float p3 = ex2(s[nt][3] - newm1);
            unsigned lo = pack_h2(p0, p1);
            unsigned hi = pack_h2(p2, p3);
            pa4[nt >> 1][(nt & 1) ? 2 : 0] = lo;
            pa4[nt >> 1][(nt & 1) ? 3 : 1] = hi;
        }

        // rescale O + li-accumulator, then AV (+ constant ones-frag row-sum)
        #pragma unroll
        for (int nt = 0; nt < 8; nt++) {
            o[nt][0] *= alpha0; o[nt][1] *= alpha0;
            o[nt][2] *= alpha1; o[nt][3] *= alpha1;
        }
        osum[0] *= alpha0; osum[1] *= alpha0;
        osum[2] *= alpha1; osum[3] *= alpha1;
        #pragma unroll
        for (int kc = 0; kc < 4; kc++) {
            #pragma unroll
            for (int pr = 0; pr < 4; pr++) {
                unsigned bb[4];
                ldsm4(bb, VTb + (pr*16 + bnp + bn8) * VTL + kc*16 + bkh);
                mma_f16(o[2*pr],     pa4[kc], &bb[0]);
                mma_f16(o[2*pr + 1], pa4[kc], &bb[2]);
            }
            mma_f16(osum, pa4[kc], onesf);   // col 0 accumulates row-sum
        }
    }

    // finalize: li = osum col0 (held by t4==0 lanes) — broadcast across quad
    int src = lane & ~3;
    float li0 = __shfl_sync(0xffffffffu, osum[0], src);
    float li1 = __shfl_sync(0xffffffffu, osum[2], src);
    float inv0 = 1.f / li0, inv1 = 1.f / li1;
    int r0 = wr + g;
    __half* ob1 = g_att + ((size_t)(b * LL + q0 + r0))     * INNER + h * DH;
    __half* ob2 = g_att + ((size_t)(b * LL + q0 + r0 + 8)) * INNER + h * DH;
    #pragma unroll
    for (int nt = 0; nt < 8; nt++) {
        int dh0 = nt*8 + t4*2;
        *(__half2*)(ob1 + dh0) = __floats2half2_rn(o[nt][0] * inv0, o[nt][1] * inv0);
        *(__half2*)(ob2 + dh0) = __floats2half2_rn(o[nt][2] * inv1, o[nt][3] * inv1);
    }
}

// ---------------- launch ----------------
extern "C" void kernel_launch(void* const* d_in, const int* in_sizes, int n_in,
                              void* d_out, int out_size) {
    const float* x      = (const float*)d_in[0];
    const float* gamma  = (const float*)d_in[1];
    const float* beta   = (const float*)d_in[2];
    const float* w_qkv  = (const float*)d_in[3];
    const float* b_qkv  = (const float*)d_in[4];
    const float* w_pos  = (const float*)d_in[5];
    const float* w_out  = (const float*)d_in[6];
    const float* b_out  = (const float*)d_in[7];
    const float* u_bias = (const float*)d_in[8];
    const float* v_bias = (const float*)d_in[9];
    float* out = (float*)d_out;

    // 1. freq table (tiny)
    freq_kernel<<<2, 256>>>();

    // 2. fused LayerNorm + PE table + weight conversion (one launch)
    ln_pe_cvt_kernel<<<LN_BLKS + PE_BLKS + CVT_BLKS, 256>>>(
        x, gamma, beta, w_qkv, w_pos, w_out);

    // 3. fused QKV GEMM + pos GEMM
    {
        dim3 grid((3 * INNER) / 128, ROWS / 128, 2);
        gemm_fused<<<grid, 256>>>(b_qkv);
    }

    // 4. attention
    {
        int smem = ATT_SMEM_BYTES;   // ~86 KB
        cudaFuncSetAttribute(attn_tc, cudaFuncAttributeMaxDynamicSharedMemorySize, smem);
        dim3 grid(LL / 128, BB * HH);
        attn_tc<<<grid, 256, smem>>>(u_bias, v_bias);
    }

    // 5. out projection -> d_out
    {
        dim3 grid(DD / 128, ROWS / 128);
        gemm_out<<<grid, 256>>>(b_out, out);
    }
}

// round 16
// speedup vs baseline: 2.6171x; 1.0295x over previous
#include <cuda_runtime.h>
#include <cuda_fp16.h>
#include <math.h>

// Problem constants
#define BB 8
#define LL 1024
#define DD 512
#define HH 8
#define DH 64
#define INNER 512
#define ROWS (BB*LL)          // 8192
#define EPSV 1e-5f
#define SCALE_LOG2E 0.18033688011112042f   // 0.125 * log2(e)

// ---------------- scratch (device globals; no allocation) ----------------
__device__ __half  g_xn [ROWS*DD];
__device__ __half  g_pe [LL*DD];
__device__ __half  g_pos[HH*LL*DH];
__device__ __half  g_q  [BB*HH*LL*DH];
__device__ __half  g_k  [BB*HH*LL*DH];
__device__ __half  g_v  [BB*HH*DH*LL];     // TRANSPOSED: [bh][dh][l]
__device__ __half  g_att[ROWS*INNER];
__device__ __half  g_wqkv[3*INNER*DD];
__device__ __half  g_wpos[INNER*DD];
__device__ __half  g_wout[DD*INNER];
__device__ double  g_freq[DD];

// ---------------- helpers ----------------
__device__ __forceinline__ void mma_f16(float c[4], const unsigned a[4], const unsigned b[2]) {
    asm volatile(
        "mma.sync.aligned.m16n8k16.row.col.f32.f16.f16.f32 "
        "{%0,%1,%2,%3}, {%4,%5,%6,%7}, {%8,%9}, {%0,%1,%2,%3};"
        : "+f"(c[0]), "+f"(c[1]), "+f"(c[2]), "+f"(c[3])
        : "r"(a[0]), "r"(a[1]), "r"(a[2]), "r"(a[3]), "r"(b[0]), "r"(b[1]));
}

__device__ __forceinline__ void ldsm4(unsigned r[4], const __half* p) {
    unsigned addr = (unsigned)__cvta_generic_to_shared((void*)p);
    asm volatile("ldmatrix.sync.aligned.m8n8.x4.shared.b16 {%0,%1,%2,%3}, [%4];"
        : "=r"(r[0]), "=r"(r[1]), "=r"(r[2]), "=r"(r[3]) : "r"(addr));
}

__device__ __forceinline__ unsigned pack_h2(float x, float y) {
    unsigned r;
    asm("cvt.rn.f16x2.f32 %0, %1, %2;" : "=r"(r) : "f"(y), "f"(x));
    return r;
}

__device__ __forceinline__ float ex2(float x) {
    float r;
    asm("ex2.approx.ftz.f32 %0, %1;" : "=f"(r) : "f"(x));
    return r;
}

// two fp16 2^x in one MUFU op
__device__ __forceinline__ unsigned ex2_h2(unsigned x) {
    unsigned r;
    asm("ex2.approx.f16x2 %0, %1;" : "=r"(r) : "r"(x));
    return r;
}

__device__ __forceinline__ void cpa16(void* dst_smem, const void* src) {
    unsigned d = (unsigned)__cvta_generic_to_shared(dst_smem);
    asm volatile("cp.async.cg.shared.global [%0], [%1], 16;" :: "r"(d), "l"(src));
}
#define CP_COMMIT asm volatile("cp.async.commit_group;")
#define CP_WAIT0  asm volatile("cp.async.wait_group 0;")

// ---------------- freq table (tiny, must precede fused kernel) ------------
__global__ void freq_kernel() {
    int j = threadIdx.x + blockIdx.x * blockDim.x;
    if (j < DD) g_freq[j] = exp(-(double)j * (log(10000.0) / 256.0));
}

// ---------------- fused LayerNorm + PE table + weight conversion ----------
#define LN_BLKS   (ROWS / 8)              // 1024
#define PE_BLKS   ((LL * DD) / 256)       // 2048
#define CVT_N4    ((3*INNER*DD + INNER*DD + DD*INNER) / 4)   // 327680
#define CVT_BLKS  ((CVT_N4 + 255) / 256)  // 1280
__global__ void ln_pe_cvt_kernel(const float* __restrict__ x,
                                 const float* __restrict__ gamma,
                                 const float* __restrict__ beta,
                                 const float* __restrict__ wq,
                                 const float* __restrict__ wp,
                                 const float* __restrict__ wo) {
    int tid = threadIdx.x, lane = tid & 31, warp = tid >> 5;
    if (blockIdx.x < LN_BLKS) {
        int row = blockIdx.x * 8 + warp;
        const float* xr = x + (size_t)row * DD;
        float4 v[4];
        float s = 0.f, sq = 0.f;
        #pragma unroll
        for (int k = 0; k < 4; k++) {
            v[k] = *(const float4*)(xr + k * 128 + lane * 4);
            s  += v[k].x + v[k].y + v[k].z + v[k].w;
            sq += v[k].x*v[k].x + v[k].y*v[k].y + v[k].z*v[k].z + v[k].w*v[k].w;
        }
        #pragma unroll
        for (int o = 16; o; o >>= 1) {
            s  += __shfl_xor_sync(0xffffffffu, s,  o);
            sq += __shfl_xor_sync(0xffffffffu, sq, o);
        }
        float mu  = s * (1.f / DD);
        float var = fmaxf(sq * (1.f / DD) - mu * mu, 0.f);
        float rs  = rsqrtf(var + EPSV);
        __half* o = g_xn + (size_t)row * DD;
        #pragma unroll
        for (int k = 0; k < 4; k++) {
            int c = k * 128 + lane * 4;
            float4 gm = *(const float4*)(gamma + c);
            float4 bt = *(const float4*)(beta + c);
            *(__half2*)(o + c)     = __floats2half2_rn((v[k].x - mu)*rs*gm.x + bt.x,
                                                       (v[k].y - mu)*rs*gm.y + bt.y);
            *(__half2*)(o + c + 2) = __floats2half2_rn((v[k].z - mu)*rs*gm.z + bt.z,
                                                       (v[k].w - mu)*rs*gm.w + bt.w);
        }
    } else if (blockIdx.x < LN_BLKS + PE_BLKS) {
        int idx = (blockIdx.x - LN_BLKS) * 256 + tid;
        int i = idx >> 9;
        int j = idx & 511;
        double angle = (double)(i - j) * g_freq[j];
        double n = rint(angle * 0.15915494309189535);   // 1/(2*pi)
        double r = angle - n * 6.283185307179586;       // reduced to [-pi, pi]
        float rf = (float)r;
        g_pe[idx] = __float2half_rn(((j & 1) == 0) ? cosf(rf) : sinf(rf));
    } else {
        const int n1 = 3*INNER*DD/4, n2 = INNER*DD/4, n3 = DD*INNER/4;
        int i = (blockIdx.x - LN_BLKS - PE_BLKS) * 256 + tid;
        float4 v; __half* dst;
        if (i < n1) {
            v = ((const float4*)wq)[i]; dst = g_wqkv + 4*i;
        } else if (i < n1 + n2) {
            v = ((const float4*)wp)[i - n1]; dst = g_wpos + 4*(i - n1);
        } else if (i < n1 + n2 + n3) {
            v = ((const float4*)wo)[i - n1 - n2]; dst = g_wout + 4*(i - n1 - n2);
        } else return;
        *(__half2*)(dst)     = __floats2half2_rn(v.x, v.y);
        *(__half2*)(dst + 2) = __floats2half2_rn(v.z, v.w);
    }
}

// ---------------- FP16 TC GEMM body, 128x128 tile, K-stage 64, dbl buffer --
#define HLD 72
#define GSTAGE (128 * HLD)
template<int MODE>
__device__ __forceinline__ void gemm_body(__half* As, __half* Bs,
                        const __half* __restrict__ A, const __half* __restrict__ Bt,
                        const float* __restrict__ bias, float* __restrict__ C,
                        int M, int N, int K, int bxx, int byy) {
    int tid  = threadIdx.x, lane = tid & 31, warp = tid >> 5;
    int wm = warp >> 2, wn = warp & 3;     // 2 x 4, warp tile 64x32
    int g  = lane >> 2, t4 = lane & 3;
    int bm = byy * 128, bn = bxx * 128;
    // LDSM per-lane addressing
    int l15 = lane & 15, lh = (lane >> 4) << 3;                 // A: row, k-half
    int bn8 = lane & 7, bkh = ((lane >> 3) & 1) << 3, bnp = (lane >> 4) << 3; // B

    float c[4][4][4];
    #pragma unroll
    for (int mt = 0; mt < 4; mt++)
        #pragma unroll
        for (int nt = 0; nt < 4; nt++)
            #pragma unroll
            for (int i = 0; i < 4; i++) c[mt][nt][i] = 0.f;

    int nstg = K >> 6;   // K/64
    int ldr = tid >> 1, ldc = (tid & 1) << 5;   // 128 rows x 2 half-chunks(32)
    // hoisted prefetch pointers (advance by 64 per stage)
    const __half* pa = A  + (size_t)(bm + ldr) * K + ldc;
    const __half* pb = Bt + (size_t)(bn + ldr) * K + ldc;
    __half* da0 = As + ldr * HLD + ldc;
    __half* db0 = Bs + ldr * HLD + ldc;
    {
        cpa16(da0, pa); cpa16(da0 + 8, pa + 8); cpa16(da0 + 16, pa + 16); cpa16(da0 + 24, pa + 24);
        cpa16(db0, pb); cpa16(db0 + 8, pb + 8); cpa16(db0 + 16, pb + 16); cpa16(db0 + 24, pb + 24);
        CP_COMMIT;
        pa += 64; pb += 64;
    }
    for (int s = 0; s < nstg; s++) {
        CP_WAIT0; __syncthreads();
        if (s + 1 < nstg) {
            int buf = (s + 1) & 1;
            __half* da = da0 + buf * GSTAGE;
            __half* db = db0 + buf * GSTAGE;
            cpa16(da, pa); cpa16(da + 8, pa + 8); cpa16(da + 16, pa + 16); cpa16(da + 24, pa + 24);
            cpa16(db, pb); cpa16(db + 8, pb + 8); cpa16(db + 16, pb + 16); cpa16(db + 24, pb + 24);
            CP_COMMIT;
            pa += 64; pb += 64;
        }
        const __half* Ab = As + (s & 1) * GSTAGE;
        const __half* Bb = Bs + (s & 1) * GSTAGE;
        #pragma unroll
        for (int kk = 0; kk < 64; kk += 16) {
            unsigned a[4][4], b01[4], b23[4];
            #pragma unroll
            for (int mt = 0; mt < 4; mt++)
                ldsm4(a[mt], Ab + (wm*64 + mt*16 + l15) * HLD + kk + lh);
            ldsm4(b01, Bb + (wn*32 +      bnp + bn8) * HLD + kk + bkh);
            ldsm4(b23, Bb + (wn*32 + 16 + bnp + bn8) * HLD + kk + bkh);
            #pragma unroll
            for (int mt = 0; mt < 4; mt++) {
                mma_f16(c[mt][0], a[mt], &b01[0]);
                mma_f16(c[mt][1], a[mt], &b01[2]);
                mma_f16(c[mt][2], a[mt], &b23[0]);
                mma_f16(c[mt][3], a[mt], &b23[2]);
            }
        }
        // no trailing barrier: next iteration's leading sync orders reuse
    }

    // epilogue (paired stores where destinations are contiguous)
    #pragma unroll
    for (int mt = 0; mt < 4; mt++) {
        #pragma unroll
        for (int nt = 0; nt < 4; nt++) {
            int r0 = bm + wm*64 + mt*16 + g;
            int c0 = bn + wn*32 + nt*8 + t4*2;
            #pragma unroll
            for (int half_ = 0; half_ < 2; half_++) {
                int r = r0 + (half_ ? 8 : 0);
                float v0 = c[mt][nt][2*half_ + 0] + (bias ? bias[c0]     : 0.f);
                float v1 = c[mt][nt][2*half_ + 1] + (bias ? bias[c0 + 1] : 0.f);
                if (MODE == 0) {
                    *(float2*)(C + (size_t)r * N + c0) = make_float2(v0, v1);
                } else if (MODE == 1) {
                    int which = c0 >> 9, rem = c0 & 511;
                    int h = rem >> 6, dh = rem & 63;
                    int b_ = r >> 10, l = r & 1023;
                    if (which == 0)
                        *(__half2*)(g_q + (((size_t)b_ * HH + h) * LL + l) * DH + dh)
                            = __floats2half2_rn(v0, v1);
                    else if (which == 1)
                        *(__half2*)(g_k + (((size_t)b_ * HH + h) * LL + l) * DH + dh)
                            = __floats2half2_rn(v0, v1);
                    else {  // V transposed: [bh][dh][l] — dh not contiguous
                        g_v[(((size_t)b_ * HH + h) * DH + dh)     * LL + l] = __float2half_rn(v0);
                        g_v[(((size_t)b_ * HH + h) * DH + dh + 1) * LL + l] = __float2half_rn(v1);
                    }
                } else {
                    int h = c0 >> 6, dh = c0 & 63;
                    *(__half2*)(g_pos + ((size_t)h * LL + r) * DH + dh)
                        = __floats2half2_rn(v0, v1);
                }
            }
        }
    }
}

// compact 1D grid: blocks 0..767 = QKV (12 x 64), 768..799 = pos (4 x 8)
__global__ __launch_bounds__(256, 2) void gemm_fused(const float* __restrict__ b_qkv) {
    __shared__ __half As[2 * GSTAGE];
    __shared__ __half Bs[2 * GSTAGE];
    int bid = blockIdx.x;
    if (bid < 768) {
        gemm_body<1>(As, Bs, g_xn, g_wqkv, b_qkv, nullptr, ROWS, 3*INNER, DD,
                     bid % 12, bid / 12);
    } else {
        int r = bid - 768;
        gemm_body<2>(As, Bs, g_pe, g_wpos, nullptr, nullptr, LL, INNER, DD,
                     r % 4, r / 4);
    }
}

__global__ __launch_bounds__(256, 2) void gemm_out(const float* __restrict__ b_out,
                                                   float* __restrict__ out) {
    __shared__ __half As[2 * GSTAGE];
    __shared__ __half Bs[2 * GSTAGE];
    gemm_body<0>(As, Bs, g_att, g_wout, b_out, out, ROWS, DD, INNER,
                 blockIdx.x, blockIdx.y);
}

// ---------------- flash attention: log2 softmax, f16x2 ex2, ones-frag li ---
#define ATL  136   // sA / sKP row stride (halves)
#define VTL  72    // sVT row stride (halves)
#define N_SA  (128 * ATL)
#define N_SKP (2 * 64 * ATL)
#define N_SVT (2 * 64 * VTL)
#define ATT_SMEM_BYTES ((N_SA + N_SKP + N_SVT) * 2)   // ~86 KB

__global__ __launch_bounds__(256, 2) void attn_tc(const float* __restrict__ u_bias,
                                                  const float* __restrict__ v_bias) {
    extern __shared__ char smbase[];
    __half* sA  = (__half*)smbase;
    __half* sKP = sA  + N_SA;
    __half* sVT = sKP + N_SKP;

    int tid = threadIdx.x, lane = tid & 31, warp = tid >> 5;
    int g  = lane >> 2, t4 = lane & 3;
    int wr = warp * 16;
    int bh = blockIdx.y, b = bh >> 3, h = bh & 7;
    int q0 = blockIdx.x * 128;
    int l15 = lane & 15, lh = (lane >> 4) << 3;
    int bn8 = lane & 7, bkh = ((lane >> 3) & 1) << 3, bnp = (lane >> 4) << 3;

    // constant ones B-fragment: row 0 of the virtual ones-matrix
    unsigned onesf[2];
    onesf[0] = onesf[1] = (g == 0) ? 0x3C003C00u : 0u;

    const __half* qb  = g_q   + (size_t)bh * LL * DH;
    const __half* kb  = g_k   + (size_t)bh * LL * DH;
    const __half* vtb = g_v   + (size_t)bh * DH * LL;
    const __half* pb  = g_pos + (size_t)h  * LL * DH;

    // hoisted prefetch pointers: thread covers rows m0 and m0+32, column c8
    int m0 = tid >> 3, c8 = (tid & 7) << 3;
    const __half* pk = kb  + (size_t)m0 * DH + c8;
    const __half* pp = pb  + (size_t)m0 * DH + c8;
    const __half* pv = vtb + (size_t)m0 * LL + c8;
    __half* dK0 = sKP + m0 * ATL + c8;
    __half* dV0 = sVT + m0 * VTL + c8;

    // prologue: stage 0
    cpa16(dK0,                pk);
    cpa16(dK0 + 32*ATL,       pk + 32*DH);
    cpa16(dK0 + 64,           pp);
    cpa16(dK0 + 32*ATL + 64,  pp + 32*DH);
    cpa16(dV0,                pv);
    cpa16(dV0 + 32*VTL,       pv + 32*LL);
    CP_COMMIT;
    pk += 64*DH; pp += 64*DH; pv += 64;

    // build sA = (Q+u | Q+v) * 0.125*log2e  (half, vectorized 16B)
    for (int idx = tid; idx < 1024; idx += 256) {
        int r = idx >> 3, cc = (idx & 7) << 3;
        uint4 qv = *(const uint4*)(qb + (size_t)(q0 + r) * DH + cc);
        const float* up = u_bias + h * DH + cc;
        const float* vp = v_bias + h * DH + cc;
        float4 u0 = *(const float4*)(up), u1 = *(const float4*)(up + 4);
        float4 v0 = *(const float4*)(vp), v1 = *(const float4*)(vp + 4);
        float2 qa = __half22float2(*(const __half2*)&qv.x);
        float2 qbv = __half22float2(*(const __half2*)&qv.y);
        float2 qc = __half22float2(*(const __half2*)&qv.z);
        float2 qd = __half22float2(*(const __half2*)&qv.w);
        uint4 wu, wv;
        wu.x = pack_h2((qa.x + u0.x) * SCALE_LOG2E, (qa.y + u0.y) * SCALE_LOG2E);
        wu.y = pack_h2((qbv.x + u0.z) * SCALE_LOG2E, (qbv.y + u0.w) * SCALE_LOG2E);
        wu.z = pack_h2((qc.x + u1.x) * SCALE_LOG2E, (qc.y + u1.y) * SCALE_LOG2E);
        wu.w = pack_h2((qd.x + u1.z) * SCALE_LOG2E, (qd.y + u1.w) * SCALE_LOG2E);
        wv.x = pack_h2((qa.x + v0.x) * SCALE_LOG2E, (qa.y + v0.y) * SCALE_LOG2E);
        wv.y = pack_h2((qbv.x + v0.z) * SCALE_LOG2E, (qbv.y + v0.w) * SCALE_LOG2E);
        wv.z = pack_h2((qc.x + v1.x) * SCALE_LOG2E, (qc.y + v1.y) * SCALE_LOG2E);
        wv.w = pack_h2((qd.x + v1.z) * SCALE_LOG2E, (qd.y + v1.w) * SCALE_LOG2E);
        *(uint4*)(sA + r * ATL + cc)      = wu;
        *(uint4*)(sA + r * ATL + 64 + cc) = wv;
    }

    float mi0 = -INFINITY, mi1 = -INFINITY;
    float o[8][4], osum[4];
    #pragma unroll
    for (int nt = 0; nt < 8; nt++)
        #pragma unroll
        for (int i = 0; i < 4; i++) o[nt][i] = 0.f;
    #pragma unroll
    for (int i = 0; i < 4; i++) osum[i] = 0.f;

    for (int kt = 0; kt < LL / 64; kt++) {
        CP_WAIT0;
        __syncthreads();
        int cur = kt & 1;
        if (kt + 1 < LL / 64) {
            int nb = (kt + 1) & 1;
            __half* dK = dK0 + nb * 64 * ATL;
            __half* dV = dV0 + nb * 64 * VTL;
            cpa16(dK,               pk);
            cpa16(dK + 32*ATL,      pk + 32*DH);
            cpa16(dK + 64,          pp);
            cpa16(dK + 32*ATL + 64, pp + 32*DH);
            cpa16(dV,               pv);
            cpa16(dV + 32*VTL,      pv + 32*LL);
            CP_COMMIT;
            pk += 64*DH; pp += 64*DH; pv += 64;
        }
        const __half* KPb = sKP + cur * 64 * ATL;
        const __half* VTb = sVT + cur * 64 * VTL;

        // scores (log2 units): warp tile 16(m) x 64(n), K=128
        float s[8][4];
        #pragma unroll
        for (int nt = 0; nt < 8; nt++)
            #pragma unroll
            for (int i = 0; i < 4; i++) s[nt][i] = 0.f;
        #pragma unroll
        for (int kk = 0; kk < 128; kk += 16) {
            unsigned a[4];
            ldsm4(a, sA + (wr + l15) * ATL + kk + lh);
            #pragma unroll
            for (int pr = 0; pr < 4; pr++) {
                unsigned bb[4];
                ldsm4(bb, KPb + (pr*16 + bnp + bn8) * ATL + kk + bkh);
                mma_f16(s[2*pr],     a, &bb[0]);
                mma_f16(s[2*pr + 1], a, &bb[2]);
            }
        }

        // register softmax (log2 units)
        float m0f = -INFINITY, m1f = -INFINITY;
        #pragma unroll
        for (int nt = 0; nt < 8; nt++) {
            m0f = fmaxf(m0f, fmaxf(s[nt][0], s[nt][1]));
            m1f = fmaxf(m1f, fmaxf(s[nt][2], s[nt][3]));
        }
        m0f = fmaxf(m0f, __shfl_xor_sync(0xffffffffu, m0f, 1));
        m0f = fmaxf(m0f, __shfl_xor_sync(0xffffffffu, m0f, 2));
        m1f = fmaxf(m1f, __shfl_xor_sync(0xffffffffu, m1f, 1));
        m1f = fmaxf(m1f, __shfl_xor_sync(0xffffffffu, m1f, 2));
        float newm0 = fmaxf(mi0, m0f), newm1 = fmaxf(mi1, m1f);
        float alpha0 = ex2(mi0 - newm0), alpha1 = ex2(mi1 - newm1);
        mi0 = newm0; mi1 = newm1;
        unsigned pa4[4][4];
        #pragma unroll
        for (int nt = 0; nt < 8; nt++) {
            // pack (s - m) as half2, single f16x2 ex2 per pair
            unsigned dlo = pack_h2(s[nt][0] - newm0, s[nt][1] - newm0);
            unsigned dhi = pack_h2(s[nt][2] - newm1, s[nt][3] - newm1);
            pa4[nt >> 1][(nt & 1) ? 2 : 0] = ex2_h2(dlo);
            pa4[nt >> 1][(nt & 1) ? 3 : 1] = ex2_h2(dhi);
        }

        // rescale O + li-accumulator, then AV (+ constant ones-frag row-sum)
        #pragma unroll
        for (int nt = 0; nt < 8; nt++) {
            o[nt][0] *= alpha0; o[nt][1] *= alpha0;
            o[nt][2] *= alpha1; o[nt][3] *= alpha1;
        }
        osum[0] *= alpha0; osum[1] *= alpha0;
        osum[2] *= alpha1; osum[3] *= alpha1;
        #pragma unroll
        for (int kc = 0; kc < 4; kc++) {
            #pragma unroll
            for (int pr = 0; pr < 4; pr++) {
                unsigned bb[4];
                ldsm4(bb, VTb + (pr*16 + bnp + bn8) * VTL + kc*16 + bkh);
                mma_f16(o[2*pr],     pa4[kc], &bb[0]);
                mma_f16(o[2*pr + 1], pa4[kc], &bb[2]);
            }
            mma_f16(osum, pa4[kc], onesf);   // col 0 accumulates row-sum
        }
    }

    // finalize: li = osum col0 (held by t4==0 lanes) — broadcast across quad
    int src = lane & ~3;
    float li0 = __shfl_sync(0xffffffffu, osum[0], src);
    float li1 = __shfl_sync(0xffffffffu, osum[2], src);
    float inv0 = 1.f / li0, inv1 = 1.f / li1;
    int r0 = wr + g;
    __half* ob1 = g_att + ((size_t)(b * LL + q0 + r0))     * INNER + h * DH;
    __half* ob2 = g_att + ((size_t)(b * LL + q0 + r0 + 8)) * INNER + h * DH;
    #pragma unroll
    for (int nt = 0; nt < 8; nt++) {
        int dh0 = nt*8 + t4*2;
        *(__half2*)(ob1 + dh0) = __floats2half2_rn(o[nt][0] * inv0, o[nt][1] * inv0);
        *(__half2*)(ob2 + dh0) = __floats2half2_rn(o[nt][2] * inv1, o[nt][3] * inv1);
    }
}

// ---------------- launch ----------------
extern "C" void kernel_launch(void* const* d_in, const int* in_sizes, int n_in,
                              void* d_out, int out_size) {
    const float* x      = (const float*)d_in[0];
    const float* gamma  = (const float*)d_in[1];
    const float* beta   = (const float*)d_in[2];
    const float* w_qkv  = (const float*)d_in[3];
    const float* b_qkv  = (const float*)d_in[4];
    const float* w_pos  = (const float*)d_in[5];
    const float* w_out  = (const float*)d_in[6];
    const float* b_out  = (const float*)d_in[7];
    const float* u_bias = (const float*)d_in[8];
    const float* v_bias = (const float*)d_in[9];
    float* out = (float*)d_out;

    // 1. freq table (tiny)
    freq_kernel<<<2, 256>>>();

    // 2. fused LayerNorm + PE table + weight conversion (one launch)
    ln_pe_cvt_kernel<<<LN_BLKS + PE_BLKS + CVT_BLKS, 256>>>(
        x, gamma, beta, w_qkv, w_pos, w_out);

    // 3. fused QKV GEMM + pos GEMM (compact 1D grid: 768 + 32 blocks)
    gemm_fused<<<800, 256>>>(b_qkv);

    // 4. attention
    {
        int smem = ATT_SMEM_BYTES;   // ~86 KB
        cudaFuncSetAttribute(attn_tc, cudaFuncAttributeMaxDynamicSharedMemorySize, smem);
        dim3 grid(LL / 128, BB * HH);
        attn_tc<<<grid, 256, smem>>>(u_bias, v_bias);
    }

    // 5. out projection -> d_out
    {
        dim3 grid(DD / 128, ROWS / 128);
        gemm_out<<<grid, 256>>>(b_out, out);
    }
}